// round 14
// baseline (speedup 1.0000x reference)
#include <cuda_runtime.h>
#include <cuda_fp16.h>
#include <math.h>
#include <stdint.h>

#define BB 2
#define SS 2048
#define DD 1024
#define NH 16
#define DH 64
#define NE 8
#define FF 4096
#define TT (BB*SS)
#define NMAIN (TT*DD)

typedef __half fp16;

__device__ fp16  g_xn[TT*DD];
__device__ fp16  g_xn2[TT*DD];
__device__ fp16  g_qkv[3][(size_t)TT*DD];
__device__ fp16  g_ctx[TT*DD];
__device__ float g_x2[TT*DD];
__device__ fp16  g_wpt[4*DD*DD];
__device__ fp16  g_w1t[(size_t)NE*DD*FF];
__device__ fp16  g_w2t[(size_t)NE*DD*FF];
__device__ fp16  g_H[(size_t)NE*TT*FF];
__device__ fp16  g_Y[(size_t)NE*TT*DD];
__device__ float g_probs[TT*NE];
__device__ float g_zz[TT];
__device__ int   g_cnt[NE];
__device__ int   g_rowlist[NE*TT];
__device__ int   g_slot_e[2*TT];
__device__ int   g_slot_r[2*TT];
__device__ float g_slot_w[2*TT];

__device__ __forceinline__ uint32_t smem_u32(const void* p) {
    uint32_t a;
    asm("{ .reg .u64 t; cvta.to.shared.u64 t, %1; cvt.u32.u64 %0, t; }" : "=r"(a) : "l"(p));
    return a;
}
__device__ __forceinline__ uint32_t elect1() {
    uint32_t p;
    asm volatile("{\n.reg .pred p;\nelect.sync _|p, 0xFFFFFFFF;\nselp.b32 %0, 1, 0, p;\n}" : "=r"(p));
    return p;
}
__device__ __forceinline__ void mbar_init(uint32_t a, uint32_t n) {
    asm volatile("mbarrier.init.shared.b64 [%0], %1;" :: "r"(a), "r"(n) : "memory");
}
__device__ __forceinline__ void mbar_wait(uint32_t a, uint32_t par) {
    asm volatile(
        "{\n.reg .pred P;\nLW%=:\n"
        "mbarrier.try_wait.parity.acquire.cta.shared::cta.b64 P, [%0], %1, 0x989680;\n"
        "@P bra LD%=;\nbra LW%=;\nLD%=:\n}" :: "r"(a), "r"(par) : "memory");
}
__device__ __forceinline__ uint64_t mk_desc(uint32_t addr) {
    return ((uint64_t)2 << 61) | ((uint64_t)1 << 46) | ((uint64_t)64 << 32)
         | ((uint64_t)1 << 16) | ((addr >> 4) & 0x3FFF);
}
__device__ __forceinline__ void tc_commit(uint32_t mbar) {
#if defined(__CUDA_ARCH_FEAT_SM103_ALL)
    asm volatile("tcgen05.commit.cta_group::1.mbarrier::arrive::one.shared::cluster.b64 [%0];"
                 :: "r"(mbar) : "memory");
#endif
}
__device__ __forceinline__ void mma_f16_ss(uint32_t d, uint64_t ad, uint64_t bd,
                                           uint32_t idesc, uint32_t en) {
#if defined(__CUDA_ARCH_FEAT_SM103_ALL)
    asm volatile(
        "{\n.reg .pred p;\nsetp.ne.u32 p, %4, 0;\n"
        "tcgen05.mma.cta_group::1.kind::f16 [%0], %1, %2, %3, {%5, %5, %5, %5}, p;\n}"
        :: "r"(d), "l"(ad), "l"(bd), "r"(idesc), "r"(en), "r"(0u) : "memory");
#endif
}

#if defined(__CUDA_ARCH_FEAT_SM103_ALL)
#define TC_ALLOC(sbaddr, n) \
    asm volatile("tcgen05.alloc.cta_group::1.sync.aligned.shared::cta.b32 [%0], %1;" \
                 :: "r"(sbaddr), "r"((uint32_t)(n)) : "memory")
#define TC_RELINQ() asm volatile("tcgen05.relinquish_alloc_permit.cta_group::1.sync.aligned;")
#define TC_DEALLOC(t, n) \
    asm volatile("tcgen05.dealloc.cta_group::1.sync.aligned.b32 %0, %1;" :: "r"(t), "r"((uint32_t)(n)))
#define TC_FENCE_AFTER()  asm volatile("tcgen05.fence::after_thread_sync;" ::: "memory")
#define TC_FENCE_BEFORE() asm volatile("tcgen05.fence::before_thread_sync;" ::: "memory")
#define TC_WAIT_LD()      asm volatile("tcgen05.wait::ld.sync.aligned;" ::: "memory")
#define TC_LD_X32(r, ta) \
    asm volatile( \
        "tcgen05.ld.sync.aligned.32x32b.x32.b32 " \
        "{%0, %1, %2, %3, %4, %5, %6, %7, %8, %9, %10, %11, %12, %13, %14, %15, " \
        " %16, %17, %18, %19, %20, %21, %22, %23, %24, %25, %26, %27, %28, %29, %30, %31}, [%32];" \
        : "=r"((r)[0]),  "=r"((r)[1]),  "=r"((r)[2]),  "=r"((r)[3]), \
          "=r"((r)[4]),  "=r"((r)[5]),  "=r"((r)[6]),  "=r"((r)[7]), \
          "=r"((r)[8]),  "=r"((r)[9]),  "=r"((r)[10]), "=r"((r)[11]), \
          "=r"((r)[12]), "=r"((r)[13]), "=r"((r)[14]), "=r"((r)[15]), \
          "=r"((r)[16]), "=r"((r)[17]), "=r"((r)[18]), "=r"((r)[19]), \
          "=r"((r)[20]), "=r"((r)[21]), "=r"((r)[22]), "=r"((r)[23]), \
          "=r"((r)[24]), "=r"((r)[25]), "=r"((r)[26]), "=r"((r)[27]), \
          "=r"((r)[28]), "=r"((r)[29]), "=r"((r)[30]), "=r"((r)[31]) \
        : "r"(ta))
#endif

__device__ __forceinline__ float gelu_tanh(float x) {
    float x3 = x * x * x;
    return 0.5f * x * (1.f + tanhf(0.7978845608028654f * (x + 0.044715f * x3)));
}
__device__ __forceinline__ uint32_t pack_h2(float a, float b) {
    __half2 h = __floats2half2_rn(a, b);
    return *(uint32_t*)&h;
}

// ---------------- rmsnorm 1 ----------------
__global__ void rmsnorm_kernel(const float* __restrict__ x, const float* __restrict__ w,
                               fp16* __restrict__ yh)
{
    int row = blockIdx.x, tid = threadIdx.x;
    int d4 = tid * 4;
    float4 xv = *(const float4*)(x + (size_t)row * DD + d4);
    float s = xv.x * xv.x + xv.y * xv.y + xv.z * xv.z + xv.w * xv.w;
    __shared__ float red[8];
    for (int o = 16; o > 0; o >>= 1) s += __shfl_xor_sync(0xffffffffu, s, o);
    if ((tid & 31) == 0) red[tid >> 5] = s;
    __syncthreads();
    float tot = 0.f;
#pragma unroll
    for (int i = 0; i < 8; i++) tot += red[i];
    float inv = rsqrtf(tot / (float)DD + 1e-6f);
    float4 wv = *(const float4*)(w + d4);
    uint2 p;
    p.x = pack_h2(xv.x * inv * wv.x, xv.y * inv * wv.y);
    p.y = pack_h2(xv.z * inv * wv.z, xv.w * inv * wv.w);
    *(uint2*)(yh + (size_t)row * DD + d4) = p;
}

// ---------------- fused rmsnorm2 + router ----------------
__global__ void norm2_router_kernel(const float* __restrict__ x2, const float* __restrict__ w,
                                    const float* __restrict__ wr, fp16* __restrict__ yh)
{
    int t = blockIdx.x, tid = threadIdx.x;
    int wid = tid >> 5, lane = tid & 31;
    int d4 = tid * 4;
    float4 xv = *(const float4*)(x2 + (size_t)t * DD + d4);
    float s = xv.x * xv.x + xv.y * xv.y + xv.z * xv.z + xv.w * xv.w;
    __shared__ float red[8];
    __shared__ float lp[8][NE];
    for (int o = 16; o > 0; o >>= 1) s += __shfl_xor_sync(0xffffffffu, s, o);
    if (lane == 0) red[wid] = s;
    __syncthreads();
    float tot = 0.f;
#pragma unroll
    for (int i = 0; i < 8; i++) tot += red[i];
    float inv = rsqrtf(tot / (float)DD + 1e-6f);
    float4 wv = *(const float4*)(w + d4);
    float v0 = xv.x * inv * wv.x, v1 = xv.y * inv * wv.y;
    float v2 = xv.z * inv * wv.z, v3 = xv.w * inv * wv.w;
    uint2 ph; ph.x = pack_h2(v0, v1); ph.y = pack_h2(v2, v3);
    *(uint2*)(yh + (size_t)t * DD + d4) = ph;
    float p[NE];
#pragma unroll
    for (int e = 0; e < NE; e++)
        p[e] = v0 * wr[(d4 + 0) * NE + e] + v1 * wr[(d4 + 1) * NE + e]
             + v2 * wr[(d4 + 2) * NE + e] + v3 * wr[(d4 + 3) * NE + e];
#pragma unroll
    for (int e = 0; e < NE; e++)
        for (int o = 16; o > 0; o >>= 1) p[e] += __shfl_xor_sync(0xffffffffu, p[e], o);
    if (lane == 0)
#pragma unroll
        for (int e = 0; e < NE; e++) lp[wid][e] = p[e];
    __syncthreads();
    if (tid == 0) {
        float lg[NE];
#pragma unroll
        for (int e = 0; e < NE; e++) {
            float a = 0.f;
#pragma unroll
            for (int wgi = 0; wgi < 8; wgi++) a += lp[wgi][e];
            lg[e] = a;
        }
        float m = lg[0];
#pragma unroll
        for (int e = 1; e < NE; e++) m = fmaxf(m, lg[e]);
        float pr[NE], sum = 0.f;
#pragma unroll
        for (int e = 0; e < NE; e++) { pr[e] = expf(lg[e] - m); sum += pr[e]; }
        float invs = 1.f / sum;
#pragma unroll
        for (int e = 0; e < NE; e++) pr[e] *= invs;
        g_zz[t] = m + logf(sum);
#pragma unroll
        for (int e = 0; e < NE; e++) g_probs[t * NE + e] = pr[e];
        int i0 = 0; float b0 = pr[0];
#pragma unroll
        for (int e = 1; e < NE; e++) if (pr[e] > b0) { b0 = pr[e]; i0 = e; }
        int i1 = -1; float b1 = -1.f;
#pragma unroll
        for (int e = 0; e < NE; e++) { if (e == i0) continue; if (pr[e] > b1) { b1 = pr[e]; i1 = e; } }
        float w0 = b0 / (b0 + b1), w1 = b1 / (b0 + b1);
        int r0 = atomicAdd(&g_cnt[i0], 1); g_rowlist[i0 * TT + r0] = t;
        int r1 = atomicAdd(&g_cnt[i1], 1); g_rowlist[i1 * TT + r1] = t;
        g_slot_e[2 * t]     = i0; g_slot_r[2 * t]     = r0; g_slot_w[2 * t]     = w0;
        g_slot_e[2 * t + 1] = i1; g_slot_r[2 * t + 1] = r1; g_slot_w[2 * t + 1] = w1;
    }
}

// ---------------- weight transpose -> fp16 ----------------
__global__ void wt_convert_kernel(const float* __restrict__ W,
                                  fp16* __restrict__ Th, int K, int N)
{
    __shared__ float tile[64][68];
    size_t zoff = (size_t)blockIdx.z * K * N;
    int n0 = blockIdx.x * 64, k0 = blockIdx.y * 64;
    int tx = threadIdx.x & 15, ty = threadIdx.x >> 4;
#pragma unroll
    for (int i = 0; i < 4; i++) {
        int r = ty + 16 * i;
        *(float4*)&tile[r][tx * 4] = *(const float4*)(W + zoff + (size_t)(k0 + r) * N + n0 + tx * 4);
    }
    __syncthreads();
#pragma unroll
    for (int i = 0; i < 4; i++) {
        int n = ty + 16 * i, kk = tx * 4;
        size_t idx = zoff + (size_t)(n0 + n) * K + k0 + kk;
        *(uint2*)(Th + idx) = make_uint2(pack_h2(tile[kk][n], tile[kk + 1][n]),
                                         pack_h2(tile[kk + 2][n], tile[kk + 3][n]));
    }
}

#define GM_QKV  1
#define GM_RES  2
#define GM_MOE1 3
#define GM_MOE2 4
#define BUF_BYTES 65536
#define G_SMEM  (1024 + 2 * BUF_BYTES)   // 132096 -> 1 CTA/SM

// ---------------- tcgen05 GEMM: C[256x256], fp16, staged coalesced epilogue -
template<int MODE>
__global__ void __launch_bounds__(256, 1)
tc_gemm(const fp16* __restrict__ A, const fp16* __restrict__ B0,
        float* __restrict__ Cf, const float* __restrict__ Res,
        fp16* __restrict__ Ch, int M, int N, int K)
{
#if defined(__CUDA_ARCH__)
    extern __shared__ char sm[];
    int tid = threadIdx.x;
    int e  = blockIdx.z;
    int m0 = blockIdx.y * 256, n0 = blockIdx.x * 256;
    int Me = M;
    const fp16* B = B0;
    if (MODE == GM_MOE1 || MODE == GM_MOE2) {
        Me = g_cnt[e];
        if (m0 >= Me) return;
        B += (size_t)e * (size_t)K * N;
    } else if (MODE == GM_QKV) {
        B += (size_t)e * (size_t)K * N;
    }

#if defined(__CUDA_ARCH_FEAT_SM103_ALL)
    uint32_t sb = smem_u32(sm);
    int wid = tid >> 5, lid = tid & 31;
    int nk = K / 64;

    auto issue_fill = [&](int kc, int bufi) {
        uint32_t tb = sb + 1024 + (uint32_t)bufi * BUF_BYTES;
#pragma unroll
        for (int it = 0; it < 2; it++) {
            int task = tid + it * 256;
            if (task < 256) {
                int gr = m0 + task;
                bool val = gr < Me;
                size_t ri = 0;
                if (val) {
                    if (MODE == GM_MOE1)      ri = (size_t)g_rowlist[e * TT + gr];
                    else if (MODE == GM_MOE2) ri = (size_t)e * TT + gr;
                    else                      ri = (size_t)gr;
                }
                const char* src = (const char*)(A + ri * (size_t)K + kc * 64);
                uint32_t sz = val ? 16u : 0u;
#pragma unroll
                for (int j = 0; j < 8; j++) {
                    uint32_t off = (uint32_t)task * 128u + j * 16u;
                    uint32_t swz = off ^ ((off >> 3) & 0x70);
                    asm volatile("cp.async.cg.shared.global [%0], [%1], 16, %2;"
                                 :: "r"(tb + swz), "l"(src + j * 16), "r"(sz) : "memory");
                }
            } else {
                int row = task - 256;
                const char* src = (const char*)(B + (size_t)(n0 + row) * K + kc * 64);
#pragma unroll
                for (int j = 0; j < 8; j++) {
                    uint32_t off = (uint32_t)row * 128u + j * 16u;
                    uint32_t swz = off ^ ((off >> 3) & 0x70);
                    asm volatile("cp.async.cg.shared.global [%0], [%1], 16;"
                                 :: "r"(tb + 32768 + swz), "l"(src + j * 16) : "memory");
                }
            }
        }
        asm volatile("cp.async.commit_group;" ::: "memory");
    };

    issue_fill(0, 0);
    if (nk > 1) issue_fill(1, 1);

    if (wid == 0) { TC_ALLOC(sb, 512); TC_RELINQ(); }
    if (tid == 0) { mbar_init(sb + 8, 1); mbar_init(sb + 16, 1); }
    __syncthreads();
    uint32_t tmem;
    asm volatile("ld.shared.b32 %0, [%1];" : "=r"(tmem) : "r"(sb));

    const uint32_t IDESC = (1u << 4) | (32u << 17) | (8u << 24);
    int ph0 = 0, ph1 = 0;
    for (int kc = 0; kc < nk; kc++) {
        int b = kc & 1;
        if (kc >= 1 && kc + 1 < nk) {
            int nb = 1 - b;
            if (nb == 0) { mbar_wait(sb + 8,  (uint32_t)(ph0 & 1)); ph0++; }
            else         { mbar_wait(sb + 16, (uint32_t)(ph1 & 1)); ph1++; }
            issue_fill(kc + 1, nb);
        }
        if (kc + 1 < nk) asm volatile("cp.async.wait_group 1;" ::: "memory");
        else             asm volatile("cp.async.wait_group 0;" ::: "memory");
        asm volatile("fence.proxy.async.shared::cta;" ::: "memory");
        __syncthreads();
        if (wid == 0 && elect1()) {
            uint32_t tb = sb + 1024 + (uint32_t)b * BUF_BYTES;
            uint64_t dA0 = mk_desc(tb);
            uint64_t dA1 = mk_desc(tb + 16384);
            uint64_t dB  = mk_desc(tb + 32768);
#pragma unroll
            for (int s = 0; s < 4; s++) {
                uint32_t en0 = (kc == 0 && s == 0) ? 0u : 1u;
                mma_f16_ss(tmem,       dA0 + 2 * s, dB + 2 * s, IDESC, en0);
                mma_f16_ss(tmem + 256, dA1 + 2 * s, dB + 2 * s, IDESC, en0);
            }
            tc_commit(sb + 8 + b * 8);
        }
    }
    {
        int lb = (nk - 1) & 1;
        if (lb == 0) mbar_wait(sb + 8,  (uint32_t)(ph0 & 1));
        else         mbar_wait(sb + 16, (uint32_t)(ph1 & 1));
    }
    TC_FENCE_AFTER();

    // staged coalesced epilogue: TMEM -> smem (128x129 fp32) -> contiguous global
    int rw = wid & 3, cw = wid >> 2;
    float* Cs = (float*)(sm + 1024);
#pragma unroll 1
    for (int rb = 0; rb < 2; rb++) {
        int mb = m0 + rb * 128;
        int rows_here = Me - mb;
        if (rows_here <= 0) break;
        if (rows_here > 128) rows_here = 128;
#pragma unroll 1
        for (int p = 0; p < 2; p++) {
            uint32_t d0[32], d1[32];
            TC_LD_X32(d0, tmem + rb * 256 + p * 128 + cw * 64);
            TC_LD_X32(d1, tmem + rb * 256 + p * 128 + cw * 64 + 32);
            TC_WAIT_LD();
            TC_FENCE_BEFORE();
            __syncthreads();
            {
                int rr = rw * 32 + lid, cb = cw * 64;
#pragma unroll
                for (int j = 0; j < 32; j++) {
                    Cs[rr * 129 + cb + j]      = __uint_as_float(d0[j]);
                    Cs[rr * 129 + cb + 32 + j] = __uint_as_float(d1[j]);
                }
            }
            __syncthreads();
#pragma unroll 4
            for (int it = 0; it < 16; it++) {
                int idx4 = (it * 256 + tid) * 4;
                int rr = idx4 >> 7, cc = idx4 & 127;
                if (rr >= rows_here) continue;
                float v0 = Cs[rr * 129 + cc + 0], v1 = Cs[rr * 129 + cc + 1];
                float v2 = Cs[rr * 129 + cc + 2], v3 = Cs[rr * 129 + cc + 3];
                int colb = n0 + p * 128 + cc;
                if (MODE == GM_RES) {
                    size_t o = (size_t)(mb + rr) * N + colb;
                    float4 rs = *(const float4*)(Res + o);
                    *(float4*)(Cf + o) = make_float4(v0 + rs.x, v1 + rs.y, v2 + rs.z, v3 + rs.w);
                } else if (MODE == GM_MOE2) {
                    size_t o = ((size_t)e * TT + mb + rr) * N + colb;
                    uint2 ph; ph.x = pack_h2(v0, v1); ph.y = pack_h2(v2, v3);
                    *(uint2*)(g_Y + o) = ph;
                } else if (MODE == GM_MOE1) {
                    size_t o = ((size_t)e * TT + mb + rr) * N + colb;
                    uint2 ph;
                    ph.x = pack_h2(gelu_tanh(v0), gelu_tanh(v1));
                    ph.y = pack_h2(gelu_tanh(v2), gelu_tanh(v3));
                    *(uint2*)(Ch + o) = ph;
                } else {
                    int row = mb + rr;
                    int b2 = row >> 11, s5 = row & (SS - 1);
                    int h = colb >> 6, dh = colb & 63;
                    size_t o = (((size_t)(b2 * NH + h)) * SS + s5) * DH + dh;
                    uint2 ph; ph.x = pack_h2(v0, v1); ph.y = pack_h2(v2, v3);
                    *(uint2*)(g_qkv[e] + o) = ph;
                }
            }
            __syncthreads();
        }
    }
    if (wid == 0) { TC_DEALLOC(tmem, 512); }

#else
    // compact SIMT fallback (never runs when sm_103a SASS is loaded)
    for (int i = tid; i < 256 * 256; i += 256) {
        int rr = i >> 8, cc = i & 255;
        int row = m0 + rr;
        if (row >= Me) continue;
        size_t ri;
        if (MODE == GM_MOE1)      ri = (size_t)g_rowlist[e * TT + row];
        else if (MODE == GM_MOE2) ri = (size_t)e * TT + row;
        else                      ri = (size_t)row;
        float acc = 0.f;
        const fp16* ar = A + ri * (size_t)K;
        const fp16* br = B + (size_t)(n0 + cc) * K;
        for (int k = 0; k < K; k++)
            acc += __half2float(ar[k]) * __half2float(br[k]);
        if (MODE == GM_RES) { size_t o = (size_t)row * N + n0 + cc; Cf[o] = acc + Res[o]; }
        else if (MODE == GM_MOE2) g_Y[((size_t)e * TT + row) * N + n0 + cc] = __float2half_rn(acc);
        else if (MODE == GM_MOE1) Ch[((size_t)e * TT + row) * N + n0 + cc] = __float2half_rn(gelu_tanh(acc));
        else {
            int col = n0 + cc, b2 = row >> 11, s5 = row & (SS - 1);
            g_qkv[e][(((size_t)(b2 * NH + (col >> 6))) * SS + s5) * DH + (col & 63)] = __float2half_rn(acc);
        }
    }
#endif
#endif
}

// ---------------- tcgen05 flash attention (unchanged) ----------------------
#define SM_Q   1024
#define SM_K   17408
#define SM_VST 33792
#define SM_VT  50176
#define SM_P   66560
#define ATT_SMEM 100352

__global__ void __launch_bounds__(256, 2)
tc_attn(fp16* __restrict__ outh)
{
#if defined(__CUDA_ARCH__)
    extern __shared__ char sm[];
    int tid = threadIdx.x;
    int bh = blockIdx.x;
    int qt = blockIdx.y;

#if defined(__CUDA_ARCH_FEAT_SM103_ALL)
    uint32_t sb = smem_u32(sm);
    int wid = tid >> 5, lane = tid & 31;

    auto fill_kv = [&](int kt) {
        int arr = tid >> 7, r = tid & 127;
        const fp16* src = (arr == 0 ? g_qkv[1] : g_qkv[2]);
        uint32_t dstb = (arr == 0 ? sb + SM_K : sb + SM_VST);
        const char* s4 = (const char*)(src + ((size_t)bh * SS + kt * 128 + r) * DH);
        if (arr == 0) {
#pragma unroll
            for (int j = 0; j < 8; j++) {
                uint32_t off = (uint32_t)r * 128u + j * 16u;
                uint32_t swz = off ^ ((off >> 3) & 0x70);
                asm volatile("cp.async.cg.shared.global [%0], [%1], 16;"
                             :: "r"(dstb + swz), "l"(s4 + j * 16) : "memory");
            }
        } else {
#pragma unroll
            for (int j = 0; j < 8; j++)
                asm volatile("cp.async.cg.shared.global [%0], [%1], 16;"
                             :: "r"(dstb + (uint32_t)r * 128u + j * 16u), "l"(s4 + j * 16) : "memory");
        }
        asm volatile("cp.async.commit_group;" ::: "memory");
    };

    fill_kv(0);

    if (wid == 0) { TC_ALLOC(sb, 256); TC_RELINQ(); }
    if (tid == 0) { mbar_init(sb + 8, 1); mbar_init(sb + 16, 1); }
    __syncthreads();
    uint32_t tmem;
    asm volatile("ld.shared.b32 %0, [%1];" : "=r"(tmem) : "r"(sb));

    {
        int r = tid & 127, j0 = (tid >> 7) * 4;
        const uint4* s4 = (const uint4*)(g_qkv[0] + ((size_t)bh * SS + qt * 128 + r) * DH);
#pragma unroll
        for (int j = 0; j < 4; j++) {
            uint32_t off = (uint32_t)r * 128u + (j0 + j) * 16u;
            uint32_t swz = off ^ ((off >> 3) & 0x70);
            *(uint4*)(sm + SM_Q + swz) = s4[j0 + j];
        }
    }

    const uint32_t IDESC_S = (1u << 4) | (16u << 17) | (8u << 24);
    const uint32_t IDESC_O = (1u << 4) | (8u << 17)  | (8u << 24);
    int sph = 0, oph = 0;
    float lpart = 0.f;
    const int NKT = SS / 128;

    for (int kt = 0; kt < NKT; kt++) {
        if (kt > 0) { mbar_wait(sb + 16, (uint32_t)(oph & 1)); oph++; }
        asm volatile("cp.async.wait_group 0;" ::: "memory");
        asm volatile("fence.proxy.async.shared::cta;" ::: "memory");
        __syncthreads();

        if (wid == 0 && elect1()) {
            uint64_t dQ = mk_desc(sb + SM_Q);
            uint64_t dK = mk_desc(sb + SM_K);
#pragma unroll
            for (int ks = 0; ks < 4; ks++)
                mma_f16_ss(tmem, dQ + 2 * ks, dK + 2 * ks, IDESC_S, ks == 0 ? 0u : 1u);
            tc_commit(sb + 8);
        }

        {
            int d = tid & 63, shb = (tid >> 6) & 1, mh = tid >> 7;
            const unsigned short* vs = (const unsigned short*)(sm + SM_VST);
            char* vt = sm + SM_VT + shb * 8192;
#pragma unroll
            for (int i = 0; i < 16; i++) {
                int m = mh * 16 + i;
                int s0 = shb * 64 + 2 * m;
                uint32_t u = (uint32_t)vs[s0 * 64 + d] | ((uint32_t)vs[(s0 + 1) * 64 + d] << 16);
                uint32_t off = (uint32_t)d * 128u + m * 4u;
                uint32_t swz = off ^ ((off >> 3) & 0x70);
                *(uint32_t*)(vt + swz) = u;
            }
        }
        asm volatile("fence.proxy.async.shared::cta;" ::: "memory");
        __syncthreads();

        mbar_wait(sb + 8, (uint32_t)(sph & 1)); sph++;
        TC_FENCE_AFTER();

        if (kt + 1 < NKT) fill_kv(kt + 1);

        {
            int rw = wid & 3, cw = wid >> 2;
            uint32_t s0[32], s1[32];
            TC_LD_X32(s0, tmem + cw * 64);
            TC_LD_X32(s1, tmem + cw * 64 + 32);
            TC_WAIT_LD();
            TC_FENCE_BEFORE();
            int r = rw * 32 + lane;
            char* pb = sm + SM_P + cw * 16384;
#pragma unroll
            for (int m = 0; m < 32; m++) {
                int c0 = 2 * m, c1 = 2 * m + 1;
                float a = __uint_as_float(c0 < 32 ? s0[c0] : s1[c0 - 32]);
                float b = __uint_as_float(c1 < 32 ? s0[c1] : s1[c1 - 32]);
                float pa = __expf(a * 0.125f);
                float pbv = __expf(b * 0.125f);
                lpart += pa + pbv;
                uint32_t off = (uint32_t)r * 128u + m * 4u;
                uint32_t swz = off ^ ((off >> 3) & 0x70);
                *(uint32_t*)(pb + swz) = pack_h2(pa, pbv);
            }
        }
        asm volatile("fence.proxy.async.shared::cta;" ::: "memory");
        __syncthreads();

        if (wid == 0 && elect1()) {
#pragma unroll
            for (int kb = 0; kb < 2; kb++) {
                uint64_t dP = mk_desc(sb + SM_P + kb * 16384);
                uint64_t dV = mk_desc(sb + SM_VT + kb * 8192);
#pragma unroll
                for (int ks = 0; ks < 4; ks++) {
                    uint32_t en0 = (kt == 0 && kb == 0 && ks == 0) ? 0u : 1u;
                    mma_f16_ss(tmem + 128, dP + 2 * ks, dV + 2 * ks, IDESC_O, en0);
                }
            }
            tc_commit(sb + 16);
        }
    }
    mbar_wait(sb + 16, (uint32_t)(oph & 1)); oph++;
    TC_FENCE_AFTER();

    float* lred = (float*)(sm + SM_P);
    lred[tid] = lpart;
    __syncthreads();
    if (wid < 4) {
        uint32_t o0[32], o1[32];
        TC_LD_X32(o0, tmem + 128);
        TC_LD_X32(o1, tmem + 160);
        TC_WAIT_LD();
        TC_FENCE_BEFORE();
        int r = wid * 32 + lane;
        float inv = 1.f / (lred[r] + lred[r + 128]);
        int b = bh >> 4, h = bh & 15;
        int s = qt * 128 + r;
        uint32_t* ph = (uint32_t*)(outh + ((size_t)(b * SS + s)) * DD + h * 64);
#pragma unroll
        for (int m = 0; m < 32; m++) {
            int c0 = 2 * m, c1 = 2 * m + 1;
            float v0 = __uint_as_float(c0 < 32 ? o0[c0] : o1[c0 - 32]) * inv;
            float v1 = __uint_as_float(c1 < 32 ? o0[c1] : o1[c1 - 32]) * inv;
            ph[m] = pack_h2(v0, v1);
        }
    }
    __syncthreads();
    if (wid == 0) { TC_DEALLOC(tmem, 256); }

#else
    if (tid < 128) {
        int r = qt * 128 + tid;
        const fp16* Q = g_qkv[0] + ((size_t)bh * SS + r) * DH;
        float acc[DH];
        for (int d = 0; d < DH; d++) acc[d] = 0.f;
        float l = 0.f;
        for (int s = 0; s < SS; s++) {
            const fp16* Kp = g_qkv[1] + ((size_t)bh * SS + s) * DH;
            const fp16* Vp = g_qkv[2] + ((size_t)bh * SS + s) * DH;
            float sc = 0.f;
            for (int d = 0; d < DH; d++) sc += __half2float(Q[d]) * __half2float(Kp[d]);
            float p = expf(sc * 0.125f);
            l += p;
            for (int d = 0; d < DH; d++) acc[d] += p * __half2float(Vp[d]);
        }
        int b = bh >> 4, h = bh & 15;
        fp16* o = outh + ((size_t)(b * SS + r)) * DD + h * 64;
        for (int d = 0; d < DH; d++) o[d] = __float2half_rn(acc[d] / l);
    }
#endif
#endif
}

// ---------------- misc kernels ----------------
__global__ void zero_cnt_kernel() { if (threadIdx.x < NE) g_cnt[threadIdx.x] = 0; }

__global__ void loss_kernel(float* __restrict__ out, int out_size)
{
    int tid = threadIdx.x;
    __shared__ float red[256];
    __shared__ float sumsp[NE];
    __shared__ float sumz;
    float accp[NE];
#pragma unroll
    for (int e = 0; e < NE; e++) accp[e] = 0.f;
    float accz = 0.f;
    for (int t = tid; t < TT; t += 256) {
        float z = g_zz[t];
        accz += z * z;
#pragma unroll
        for (int e = 0; e < NE; e++) accp[e] += g_probs[t * NE + e];
    }
    red[tid] = accz; __syncthreads();
    for (int o = 128; o > 0; o >>= 1) { if (tid < o) red[tid] += red[tid + o]; __syncthreads(); }
    if (tid == 0) sumz = red[0];
    __syncthreads();
    for (int e = 0; e < NE; e++) {
        red[tid] = accp[e]; __syncthreads();
        for (int o = 128; o > 0; o >>= 1) { if (tid < o) red[tid] += red[tid + o]; __syncthreads(); }
        if (tid == 0) sumsp[e] = red[0];
        __syncthreads();
    }
    if (tid == 0) {
        float aux = 0.f;
        for (int e = 0; e < NE; e++)
            aux += ((float)g_cnt[e] / (float)TT) * (sumsp[e] / (float)TT);
        aux *= (float)NE / 2.f;
        float loss = aux + 0.001f * (sumz / (float)TT);
        for (int i = NMAIN; i < out_size; i++) out[i] = loss;
    }
}

__global__ void combine_kernel(float* __restrict__ out)
{
    int idx4 = (blockIdx.x * 256 + threadIdx.x) * 4;
    if (idx4 >= NMAIN) return;
    int t = idx4 >> 10, d = idx4 & 1023;
    int e0 = g_slot_e[2 * t], r0 = g_slot_r[2 * t];
    int e1 = g_slot_e[2 * t + 1], r1 = g_slot_r[2 * t + 1];
    float w0 = g_slot_w[2 * t], w1 = g_slot_w[2 * t + 1];
    float4 xv = *(const float4*)(g_x2 + idx4);
    uint2 y0u = *(const uint2*)(g_Y + ((size_t)e0 * TT + r0) * DD + d);
    uint2 y1u = *(const uint2*)(g_Y + ((size_t)e1 * TT + r1) * DD + d);
    __half2 a0 = *(__half2*)&y0u.x, a1 = *(__half2*)&y0u.y;
    __half2 b0 = *(__half2*)&y1u.x, b1 = *(__half2*)&y1u.y;
    float4 r;
    r.x = xv.x + w0 * __low2float(a0)  + w1 * __low2float(b0);
    r.y = xv.y + w0 * __high2float(a0) + w1 * __high2float(b0);
    r.z = xv.z + w0 * __low2float(a1)  + w1 * __low2float(b1);
    r.w = xv.w + w0 * __high2float(a1) + w1 * __high2float(b1);
    *(float4*)(out + idx4) = r;
}

// ---------------- launch ----------------
extern "C" void kernel_launch(void* const* d_in, const int* in_sizes, int n_in,
                              void* d_out, int out_size)
{
    const float* x   = (const float*)d_in[0];
    const float* ln1 = (const float*)d_in[1];
    const float* ln2 = (const float*)d_in[2];
    const float* wq  = (const float*)d_in[3];
    const float* wk  = (const float*)d_in[4];
    const float* wv  = (const float*)d_in[5];
    const float* wo  = (const float*)d_in[6];
    const float* wr  = (const float*)d_in[7];
    const float* w1  = (const float*)d_in[8];
    const float* w2  = (const float*)d_in[9];
    float* out = (float*)d_out;

    cudaFuncSetAttribute(tc_attn, cudaFuncAttributeMaxDynamicSharedMemorySize, ATT_SMEM);
    cudaFuncSetAttribute(tc_gemm<GM_QKV>,  cudaFuncAttributeMaxDynamicSharedMemorySize, G_SMEM);
    cudaFuncSetAttribute(tc_gemm<GM_RES>,  cudaFuncAttributeMaxDynamicSharedMemorySize, G_SMEM);
    cudaFuncSetAttribute(tc_gemm<GM_MOE1>, cudaFuncAttributeMaxDynamicSharedMemorySize, G_SMEM);
    cudaFuncSetAttribute(tc_gemm<GM_MOE2>, cudaFuncAttributeMaxDynamicSharedMemorySize, G_SMEM);

    fp16 *p_xn, *p_xn2, *p_ctx, *p_wpt, *p_w1t, *p_w2t, *p_H;
    float *p_x2;
    cudaGetSymbolAddress((void**)&p_xn,   g_xn);
    cudaGetSymbolAddress((void**)&p_xn2,  g_xn2);
    cudaGetSymbolAddress((void**)&p_ctx,  g_ctx);
    cudaGetSymbolAddress((void**)&p_x2,   g_x2);
    cudaGetSymbolAddress((void**)&p_wpt,  g_wpt);
    cudaGetSymbolAddress((void**)&p_w1t,  g_w1t);
    cudaGetSymbolAddress((void**)&p_w2t,  g_w2t);
    cudaGetSymbolAddress((void**)&p_H,    g_H);

    dim3 bt(256);
    wt_convert_kernel<<<dim3(DD/64, DD/64, 1), bt>>>(wq, p_wpt,           DD, DD);
    wt_convert_kernel<<<dim3(DD/64, DD/64, 1), bt>>>(wk, p_wpt + DD*DD,   DD, DD);
    wt_convert_kernel<<<dim3(DD/64, DD/64, 1), bt>>>(wv, p_wpt + 2*DD*DD, DD, DD);
    wt_convert_kernel<<<dim3(DD/64, DD/64, 1), bt>>>(wo, p_wpt + 3*DD*DD, DD, DD);

    rmsnorm_kernel<<<TT, 256>>>(x, ln1, p_xn);

    // launch 5 (ncu -s 5): QKV projections
    tc_gemm<GM_QKV><<<dim3(DD/256, TT/256, 3), 256, G_SMEM>>>(
        p_xn, p_wpt, nullptr, nullptr, nullptr, TT, DD, DD);

    wt_convert_kernel<<<dim3(FF/64, DD/64, NE), bt>>>(w1, p_w1t, DD, FF);
    wt_convert_kernel<<<dim3(DD/64, FF/64, NE), bt>>>(w2, p_w2t, FF, DD);

    tc_attn<<<dim3(BB * NH, SS / 128), 256, ATT_SMEM>>>(p_ctx);

    tc_gemm<GM_RES><<<dim3(DD/256, TT/256, 1), 256, G_SMEM>>>(
        p_ctx, p_wpt + 3*DD*DD, p_x2, x, nullptr, TT, DD, DD);

    zero_cnt_kernel<<<1, 32>>>();
    norm2_router_kernel<<<TT, 256>>>(p_x2, ln2, wr, p_xn2);
    loss_kernel<<<1, 256>>>(out, out_size);

    tc_gemm<GM_MOE1><<<dim3(FF/256, TT/256, NE), 256, G_SMEM>>>(
        p_xn2, p_w1t, nullptr, nullptr, p_H, TT, FF, DD);
    tc_gemm<GM_MOE2><<<dim3(DD/256, TT/256, NE), 256, G_SMEM>>>(
        p_H, p_w2t, nullptr, nullptr, nullptr, TT, DD, FF);

    combine_kernel<<<(NMAIN/4 + 255) / 256, 256>>>(out);
}

// round 15
// speedup vs baseline: 1.0046x; 1.0046x over previous
#include <cuda_runtime.h>
#include <cuda_fp16.h>
#include <math.h>
#include <stdint.h>

#define BB 2
#define SS 2048
#define DD 1024
#define NH 16
#define DH 64
#define NE 8
#define FF 4096
#define TT (BB*SS)
#define NMAIN (TT*DD)

typedef __half fp16;

__device__ fp16  g_xn[TT*DD];
__device__ fp16  g_xn2[TT*DD];
__device__ fp16  g_qkv[3][(size_t)TT*DD];
__device__ fp16  g_ctx[TT*DD];
__device__ float g_x2[TT*DD];
__device__ fp16  g_wpt[4*DD*DD];
__device__ fp16  g_w1t[(size_t)NE*DD*FF];
__device__ fp16  g_w2t[(size_t)NE*DD*FF];
__device__ fp16  g_H[(size_t)NE*TT*FF];
__device__ fp16  g_Y[(size_t)NE*TT*DD];
__device__ float g_probs[TT*NE];
__device__ float g_zz[TT];
__device__ int   g_cnt[NE];
__device__ int   g_rowlist[NE*TT];
__device__ int   g_slot_e[2*TT];
__device__ int   g_slot_r[2*TT];
__device__ float g_slot_w[2*TT];

__device__ __forceinline__ uint32_t smem_u32(const void* p) {
    uint32_t a;
    asm("{ .reg .u64 t; cvta.to.shared.u64 t, %1; cvt.u32.u64 %0, t; }" : "=r"(a) : "l"(p));
    return a;
}
__device__ __forceinline__ uint32_t elect1() {
    uint32_t p;
    asm volatile("{\n.reg .pred p;\nelect.sync _|p, 0xFFFFFFFF;\nselp.b32 %0, 1, 0, p;\n}" : "=r"(p));
    return p;
}
__device__ __forceinline__ void mbar_init(uint32_t a, uint32_t n) {
    asm volatile("mbarrier.init.shared.b64 [%0], %1;" :: "r"(a), "r"(n) : "memory");
}
__device__ __forceinline__ void mbar_wait(uint32_t a, uint32_t par) {
    asm volatile(
        "{\n.reg .pred P;\nLW%=:\n"
        "mbarrier.try_wait.parity.acquire.cta.shared::cta.b64 P, [%0], %1, 0x989680;\n"
        "@P bra LD%=;\nbra LW%=;\nLD%=:\n}" :: "r"(a), "r"(par) : "memory");
}
__device__ __forceinline__ uint64_t mk_desc(uint32_t addr) {
    return ((uint64_t)2 << 61) | ((uint64_t)1 << 46) | ((uint64_t)64 << 32)
         | ((uint64_t)1 << 16) | ((addr >> 4) & 0x3FFF);
}
__device__ __forceinline__ void tc_commit(uint32_t mbar) {
#if defined(__CUDA_ARCH_FEAT_SM103_ALL)
    asm volatile("tcgen05.commit.cta_group::1.mbarrier::arrive::one.shared::cluster.b64 [%0];"
                 :: "r"(mbar) : "memory");
#endif
}
__device__ __forceinline__ void mma_f16_ss(uint32_t d, uint64_t ad, uint64_t bd,
                                           uint32_t idesc, uint32_t en) {
#if defined(__CUDA_ARCH_FEAT_SM103_ALL)
    asm volatile(
        "{\n.reg .pred p;\nsetp.ne.u32 p, %4, 0;\n"
        "tcgen05.mma.cta_group::1.kind::f16 [%0], %1, %2, %3, {%5, %5, %5, %5}, p;\n}"
        :: "r"(d), "l"(ad), "l"(bd), "r"(idesc), "r"(en), "r"(0u) : "memory");
#endif
}

#if defined(__CUDA_ARCH_FEAT_SM103_ALL)
#define TC_ALLOC(sbaddr, n) \
    asm volatile("tcgen05.alloc.cta_group::1.sync.aligned.shared::cta.b32 [%0], %1;" \
                 :: "r"(sbaddr), "r"((uint32_t)(n)) : "memory")
#define TC_RELINQ() asm volatile("tcgen05.relinquish_alloc_permit.cta_group::1.sync.aligned;")
#define TC_DEALLOC(t, n) \
    asm volatile("tcgen05.dealloc.cta_group::1.sync.aligned.b32 %0, %1;" :: "r"(t), "r"((uint32_t)(n)))
#define TC_FENCE_AFTER()  asm volatile("tcgen05.fence::after_thread_sync;" ::: "memory")
#define TC_FENCE_BEFORE() asm volatile("tcgen05.fence::before_thread_sync;" ::: "memory")
#define TC_WAIT_LD()      asm volatile("tcgen05.wait::ld.sync.aligned;" ::: "memory")
#define TC_LD_X32(r, ta) \
    asm volatile( \
        "tcgen05.ld.sync.aligned.32x32b.x32.b32 " \
        "{%0, %1, %2, %3, %4, %5, %6, %7, %8, %9, %10, %11, %12, %13, %14, %15, " \
        " %16, %17, %18, %19, %20, %21, %22, %23, %24, %25, %26, %27, %28, %29, %30, %31}, [%32];" \
        : "=r"((r)[0]),  "=r"((r)[1]),  "=r"((r)[2]),  "=r"((r)[3]), \
          "=r"((r)[4]),  "=r"((r)[5]),  "=r"((r)[6]),  "=r"((r)[7]), \
          "=r"((r)[8]),  "=r"((r)[9]),  "=r"((r)[10]), "=r"((r)[11]), \
          "=r"((r)[12]), "=r"((r)[13]), "=r"((r)[14]), "=r"((r)[15]), \
          "=r"((r)[16]), "=r"((r)[17]), "=r"((r)[18]), "=r"((r)[19]), \
          "=r"((r)[20]), "=r"((r)[21]), "=r"((r)[22]), "=r"((r)[23]), \
          "=r"((r)[24]), "=r"((r)[25]), "=r"((r)[26]), "=r"((r)[27]), \
          "=r"((r)[28]), "=r"((r)[29]), "=r"((r)[30]), "=r"((r)[31]) \
        : "r"(ta))
#endif

__device__ __forceinline__ float gelu_tanh(float x) {
    float x3 = x * x * x;
    return 0.5f * x * (1.f + tanhf(0.7978845608028654f * (x + 0.044715f * x3)));
}
__device__ __forceinline__ uint32_t pack_h2(float a, float b) {
    __half2 h = __floats2half2_rn(a, b);
    return *(uint32_t*)&h;
}

// ---------------- rmsnorm 1 ----------------
__global__ void rmsnorm_kernel(const float* __restrict__ x, const float* __restrict__ w,
                               fp16* __restrict__ yh)
{
    int row = blockIdx.x, tid = threadIdx.x;
    int d4 = tid * 4;
    float4 xv = *(const float4*)(x + (size_t)row * DD + d4);
    float s = xv.x * xv.x + xv.y * xv.y + xv.z * xv.z + xv.w * xv.w;
    __shared__ float red[8];
    for (int o = 16; o > 0; o >>= 1) s += __shfl_xor_sync(0xffffffffu, s, o);
    if ((tid & 31) == 0) red[tid >> 5] = s;
    __syncthreads();
    float tot = 0.f;
#pragma unroll
    for (int i = 0; i < 8; i++) tot += red[i];
    float inv = rsqrtf(tot / (float)DD + 1e-6f);
    float4 wv = *(const float4*)(w + d4);
    uint2 p;
    p.x = pack_h2(xv.x * inv * wv.x, xv.y * inv * wv.y);
    p.y = pack_h2(xv.z * inv * wv.z, xv.w * inv * wv.w);
    *(uint2*)(yh + (size_t)row * DD + d4) = p;
}

// ---------------- fused rmsnorm2 + router ----------------
__global__ void norm2_router_kernel(const float* __restrict__ x2, const float* __restrict__ w,
                                    const float* __restrict__ wr, fp16* __restrict__ yh)
{
    int t = blockIdx.x, tid = threadIdx.x;
    int wid = tid >> 5, lane = tid & 31;
    int d4 = tid * 4;
    float4 xv = *(const float4*)(x2 + (size_t)t * DD + d4);
    float s = xv.x * xv.x + xv.y * xv.y + xv.z * xv.z + xv.w * xv.w;
    __shared__ float red[8];
    __shared__ float lp[8][NE];
    for (int o = 16; o > 0; o >>= 1) s += __shfl_xor_sync(0xffffffffu, s, o);
    if (lane == 0) red[wid] = s;
    __syncthreads();
    float tot = 0.f;
#pragma unroll
    for (int i = 0; i < 8; i++) tot += red[i];
    float inv = rsqrtf(tot / (float)DD + 1e-6f);
    float4 wv = *(const float4*)(w + d4);
    float v0 = xv.x * inv * wv.x, v1 = xv.y * inv * wv.y;
    float v2 = xv.z * inv * wv.z, v3 = xv.w * inv * wv.w;
    uint2 ph; ph.x = pack_h2(v0, v1); ph.y = pack_h2(v2, v3);
    *(uint2*)(yh + (size_t)t * DD + d4) = ph;
    float p[NE];
#pragma unroll
    for (int e = 0; e < NE; e++)
        p[e] = v0 * wr[(d4 + 0) * NE + e] + v1 * wr[(d4 + 1) * NE + e]
             + v2 * wr[(d4 + 2) * NE + e] + v3 * wr[(d4 + 3) * NE + e];
#pragma unroll
    for (int e = 0; e < NE; e++)
        for (int o = 16; o > 0; o >>= 1) p[e] += __shfl_xor_sync(0xffffffffu, p[e], o);
    if (lane == 0)
#pragma unroll
        for (int e = 0; e < NE; e++) lp[wid][e] = p[e];
    __syncthreads();
    if (tid == 0) {
        float lg[NE];
#pragma unroll
        for (int e = 0; e < NE; e++) {
            float a = 0.f;
#pragma unroll
            for (int wgi = 0; wgi < 8; wgi++) a += lp[wgi][e];
            lg[e] = a;
        }
        float m = lg[0];
#pragma unroll
        for (int e = 1; e < NE; e++) m = fmaxf(m, lg[e]);
        float pr[NE], sum = 0.f;
#pragma unroll
        for (int e = 0; e < NE; e++) { pr[e] = expf(lg[e] - m); sum += pr[e]; }
        float invs = 1.f / sum;
#pragma unroll
        for (int e = 0; e < NE; e++) pr[e] *= invs;
        g_zz[t] = m + logf(sum);
#pragma unroll
        for (int e = 0; e < NE; e++) g_probs[t * NE + e] = pr[e];
        int i0 = 0; float b0 = pr[0];
#pragma unroll
        for (int e = 1; e < NE; e++) if (pr[e] > b0) { b0 = pr[e]; i0 = e; }
        int i1 = -1; float b1 = -1.f;
#pragma unroll
        for (int e = 0; e < NE; e++) { if (e == i0) continue; if (pr[e] > b1) { b1 = pr[e]; i1 = e; } }
        float w0 = b0 / (b0 + b1), w1 = b1 / (b0 + b1);
        int r0 = atomicAdd(&g_cnt[i0], 1); g_rowlist[i0 * TT + r0] = t;
        int r1 = atomicAdd(&g_cnt[i1], 1); g_rowlist[i1 * TT + r1] = t;
        g_slot_e[2 * t]     = i0; g_slot_r[2 * t]     = r0; g_slot_w[2 * t]     = w0;
        g_slot_e[2 * t + 1] = i1; g_slot_r[2 * t + 1] = r1; g_slot_w[2 * t + 1] = w1;
    }
}

// ---------------- weight transpose -> fp16 (generic) -----------------------
__global__ void wt_convert_kernel(const float* __restrict__ W,
                                  fp16* __restrict__ Th, int K, int N)
{
    __shared__ float tile[64][68];
    size_t zoff = (size_t)blockIdx.z * K * N;
    int n0 = blockIdx.x * 64, k0 = blockIdx.y * 64;
    int tx = threadIdx.x & 15, ty = threadIdx.x >> 4;
#pragma unroll
    for (int i = 0; i < 4; i++) {
        int r = ty + 16 * i;
        *(float4*)&tile[r][tx * 4] = *(const float4*)(W + zoff + (size_t)(k0 + r) * N + n0 + tx * 4);
    }
    __syncthreads();
#pragma unroll
    for (int i = 0; i < 4; i++) {
        int n = ty + 16 * i, kk = tx * 4;
        size_t idx = zoff + (size_t)(n0 + n) * K + k0 + kk;
        *(uint2*)(Th + idx) = make_uint2(pack_h2(tile[kk][n], tile[kk + 1][n]),
                                         pack_h2(tile[kk + 2][n], tile[kk + 3][n]));
    }
}

// ---------------- fused wq/wk/wv transpose (z selects source) ---------------
__global__ void wt_convert_qkv_kernel(const float* __restrict__ Wq,
                                      const float* __restrict__ Wk,
                                      const float* __restrict__ Wv,
                                      fp16* __restrict__ Th)
{
    __shared__ float tile[64][68];
    const float* W = (blockIdx.z == 0) ? Wq : (blockIdx.z == 1 ? Wk : Wv);
    size_t zoff = (size_t)blockIdx.z * DD * DD;
    int n0 = blockIdx.x * 64, k0 = blockIdx.y * 64;
    int tx = threadIdx.x & 15, ty = threadIdx.x >> 4;
#pragma unroll
    for (int i = 0; i < 4; i++) {
        int r = ty + 16 * i;
        *(float4*)&tile[r][tx * 4] = *(const float4*)(W + (size_t)(k0 + r) * DD + n0 + tx * 4);
    }
    __syncthreads();
#pragma unroll
    for (int i = 0; i < 4; i++) {
        int n = ty + 16 * i, kk = tx * 4;
        size_t idx = zoff + (size_t)(n0 + n) * DD + k0 + kk;
        *(uint2*)(Th + idx) = make_uint2(pack_h2(tile[kk][n], tile[kk + 1][n]),
                                         pack_h2(tile[kk + 2][n], tile[kk + 3][n]));
    }
}

#define GM_QKV  1
#define GM_RES  2
#define GM_MOE1 3
#define GM_MOE2 4
#define BUF_BYTES 65536
#define G_SMEM  (1024 + 2 * BUF_BYTES)   // 132096 -> 1 CTA/SM

// ---------------- tcgen05 GEMM: C[256x256], fp16, staged coalesced epilogue -
template<int MODE>
__global__ void __launch_bounds__(256, 1)
tc_gemm(const fp16* __restrict__ A, const fp16* __restrict__ B0,
        float* __restrict__ Cf, const float* __restrict__ Res,
        fp16* __restrict__ Ch, int M, int N, int K)
{
#if defined(__CUDA_ARCH__)
    extern __shared__ char sm[];
    int tid = threadIdx.x;
    int e  = blockIdx.z;
    int m0 = blockIdx.y * 256, n0 = blockIdx.x * 256;
    int Me = M;
    const fp16* B = B0;
    if (MODE == GM_MOE1 || MODE == GM_MOE2) {
        Me = g_cnt[e];
        if (m0 >= Me) return;
        B += (size_t)e * (size_t)K * N;
    } else if (MODE == GM_QKV) {
        B += (size_t)e * (size_t)K * N;
    }

#if defined(__CUDA_ARCH_FEAT_SM103_ALL)
    uint32_t sb = smem_u32(sm);
    int wid = tid >> 5, lid = tid & 31;
    int nk = K / 64;

    auto issue_fill = [&](int kc, int bufi) {
        uint32_t tb = sb + 1024 + (uint32_t)bufi * BUF_BYTES;
#pragma unroll
        for (int it = 0; it < 2; it++) {
            int task = tid + it * 256;
            if (task < 256) {
                int gr = m0 + task;
                bool val = gr < Me;
                size_t ri = 0;
                if (val) {
                    if (MODE == GM_MOE1)      ri = (size_t)g_rowlist[e * TT + gr];
                    else if (MODE == GM_MOE2) ri = (size_t)e * TT + gr;
                    else                      ri = (size_t)gr;
                }
                const char* src = (const char*)(A + ri * (size_t)K + kc * 64);
                uint32_t sz = val ? 16u : 0u;
#pragma unroll
                for (int j = 0; j < 8; j++) {
                    uint32_t off = (uint32_t)task * 128u + j * 16u;
                    uint32_t swz = off ^ ((off >> 3) & 0x70);
                    asm volatile("cp.async.cg.shared.global [%0], [%1], 16, %2;"
                                 :: "r"(tb + swz), "l"(src + j * 16), "r"(sz) : "memory");
                }
            } else {
                int row = task - 256;
                const char* src = (const char*)(B + (size_t)(n0 + row) * K + kc * 64);
#pragma unroll
                for (int j = 0; j < 8; j++) {
                    uint32_t off = (uint32_t)row * 128u + j * 16u;
                    uint32_t swz = off ^ ((off >> 3) & 0x70);
                    asm volatile("cp.async.cg.shared.global [%0], [%1], 16;"
                                 :: "r"(tb + 32768 + swz), "l"(src + j * 16) : "memory");
                }
            }
        }
        asm volatile("cp.async.commit_group;" ::: "memory");
    };

    issue_fill(0, 0);
    if (nk > 1) issue_fill(1, 1);

    if (wid == 0) { TC_ALLOC(sb, 512); TC_RELINQ(); }
    if (tid == 0) { mbar_init(sb + 8, 1); mbar_init(sb + 16, 1); }
    __syncthreads();
    uint32_t tmem;
    asm volatile("ld.shared.b32 %0, [%1];" : "=r"(tmem) : "r"(sb));

    const uint32_t IDESC = (1u << 4) | (32u << 17) | (8u << 24);
    int ph0 = 0, ph1 = 0;
    for (int kc = 0; kc < nk; kc++) {
        int b = kc & 1;
        if (kc >= 1 && kc + 1 < nk) {
            int nb = 1 - b;
            if (nb == 0) { mbar_wait(sb + 8,  (uint32_t)(ph0 & 1)); ph0++; }
            else         { mbar_wait(sb + 16, (uint32_t)(ph1 & 1)); ph1++; }
            issue_fill(kc + 1, nb);
        }
        if (kc + 1 < nk) asm volatile("cp.async.wait_group 1;" ::: "memory");
        else             asm volatile("cp.async.wait_group 0;" ::: "memory");
        asm volatile("fence.proxy.async.shared::cta;" ::: "memory");
        __syncthreads();
        if (wid == 0 && elect1()) {
            uint32_t tb = sb + 1024 + (uint32_t)b * BUF_BYTES;
            uint64_t dA0 = mk_desc(tb);
            uint64_t dA1 = mk_desc(tb + 16384);
            uint64_t dB  = mk_desc(tb + 32768);
#pragma unroll
            for (int s = 0; s < 4; s++) {
                uint32_t en0 = (kc == 0 && s == 0) ? 0u : 1u;
                mma_f16_ss(tmem,       dA0 + 2 * s, dB + 2 * s, IDESC, en0);
                mma_f16_ss(tmem + 256, dA1 + 2 * s, dB + 2 * s, IDESC, en0);
            }
            tc_commit(sb + 8 + b * 8);
        }
    }
    {
        int lb = (nk - 1) & 1;
        if (lb == 0) mbar_wait(sb + 8,  (uint32_t)(ph0 & 1));
        else         mbar_wait(sb + 16, (uint32_t)(ph1 & 1));
    }
    TC_FENCE_AFTER();

    // staged coalesced epilogue: TMEM -> smem (128x129 fp32) -> contiguous global
    int rw = wid & 3, cw = wid >> 2;
    float* Cs = (float*)(sm + 1024);
#pragma unroll 1
    for (int rb = 0; rb < 2; rb++) {
        int mb = m0 + rb * 128;
        int rows_here = Me - mb;
        if (rows_here <= 0) break;
        if (rows_here > 128) rows_here = 128;
#pragma unroll 1
        for (int p = 0; p < 2; p++) {
            uint32_t d0[32], d1[32];
            TC_LD_X32(d0, tmem + rb * 256 + p * 128 + cw * 64);
            TC_LD_X32(d1, tmem + rb * 256 + p * 128 + cw * 64 + 32);
            TC_WAIT_LD();
            TC_FENCE_BEFORE();
            __syncthreads();
            {
                int rr = rw * 32 + lid, cb = cw * 64;
#pragma unroll
                for (int j = 0; j < 32; j++) {
                    Cs[rr * 129 + cb + j]      = __uint_as_float(d0[j]);
                    Cs[rr * 129 + cb + 32 + j] = __uint_as_float(d1[j]);
                }
            }
            __syncthreads();
#pragma unroll 4
            for (int it = 0; it < 16; it++) {
                int idx4 = (it * 256 + tid) * 4;
                int rr = idx4 >> 7, cc = idx4 & 127;
                if (rr >= rows_here) continue;
                float v0 = Cs[rr * 129 + cc + 0], v1 = Cs[rr * 129 + cc + 1];
                float v2 = Cs[rr * 129 + cc + 2], v3 = Cs[rr * 129 + cc + 3];
                int colb = n0 + p * 128 + cc;
                if (MODE == GM_RES) {
                    size_t o = (size_t)(mb + rr) * N + colb;
                    float4 rs = *(const float4*)(Res + o);
                    *(float4*)(Cf + o) = make_float4(v0 + rs.x, v1 + rs.y, v2 + rs.z, v3 + rs.w);
                } else if (MODE == GM_MOE2) {
                    size_t o = ((size_t)e * TT + mb + rr) * N + colb;
                    uint2 ph; ph.x = pack_h2(v0, v1); ph.y = pack_h2(v2, v3);
                    *(uint2*)(g_Y + o) = ph;
                } else if (MODE == GM_MOE1) {
                    size_t o = ((size_t)e * TT + mb + rr) * N + colb;
                    uint2 ph;
                    ph.x = pack_h2(gelu_tanh(v0), gelu_tanh(v1));
                    ph.y = pack_h2(gelu_tanh(v2), gelu_tanh(v3));
                    *(uint2*)(Ch + o) = ph;
                } else {
                    int row = mb + rr;
                    int b2 = row >> 11, s5 = row & (SS - 1);
                    int h = colb >> 6, dh = colb & 63;
                    size_t o = (((size_t)(b2 * NH + h)) * SS + s5) * DH + dh;
                    uint2 ph; ph.x = pack_h2(v0, v1); ph.y = pack_h2(v2, v3);
                    *(uint2*)(g_qkv[e] + o) = ph;
                }
            }
            __syncthreads();
        }
    }
    if (wid == 0) { TC_DEALLOC(tmem, 512); }

#else
    // compact SIMT fallback (never runs when sm_103a SASS is loaded)
    for (int i = tid; i < 256 * 256; i += 256) {
        int rr = i >> 8, cc = i & 255;
        int row = m0 + rr;
        if (row >= Me) continue;
        size_t ri;
        if (MODE == GM_MOE1)      ri = (size_t)g_rowlist[e * TT + row];
        else if (MODE == GM_MOE2) ri = (size_t)e * TT + row;
        else                      ri = (size_t)row;
        float acc = 0.f;
        const fp16* ar = A + ri * (size_t)K;
        const fp16* br = B + (size_t)(n0 + cc) * K;
        for (int k = 0; k < K; k++)
            acc += __half2float(ar[k]) * __half2float(br[k]);
        if (MODE == GM_RES) { size_t o = (size_t)row * N + n0 + cc; Cf[o] = acc + Res[o]; }
        else if (MODE == GM_MOE2) g_Y[((size_t)e * TT + row) * N + n0 + cc] = __float2half_rn(acc);
        else if (MODE == GM_MOE1) Ch[((size_t)e * TT + row) * N + n0 + cc] = __float2half_rn(gelu_tanh(acc));
        else {
            int col = n0 + cc, b2 = row >> 11, s5 = row & (SS - 1);
            g_qkv[e][(((size_t)(b2 * NH + (col >> 6))) * SS + s5) * DH + (col & 63)] = __float2half_rn(acc);
        }
    }
#endif
#endif
}

// ---------------- tcgen05 flash attention (unchanged) ----------------------
#define SM_Q   1024
#define SM_K   17408
#define SM_VST 33792
#define SM_VT  50176
#define SM_P   66560
#define ATT_SMEM 100352

__global__ void __launch_bounds__(256, 2)
tc_attn(fp16* __restrict__ outh)
{
#if defined(__CUDA_ARCH__)
    extern __shared__ char sm[];
    int tid = threadIdx.x;
    int bh = blockIdx.x;
    int qt = blockIdx.y;

#if defined(__CUDA_ARCH_FEAT_SM103_ALL)
    uint32_t sb = smem_u32(sm);
    int wid = tid >> 5, lane = tid & 31;

    auto fill_kv = [&](int kt) {
        int arr = tid >> 7, r = tid & 127;
        const fp16* src = (arr == 0 ? g_qkv[1] : g_qkv[2]);
        uint32_t dstb = (arr == 0 ? sb + SM_K : sb + SM_VST);
        const char* s4 = (const char*)(src + ((size_t)bh * SS + kt * 128 + r) * DH);
        if (arr == 0) {
#pragma unroll
            for (int j = 0; j < 8; j++) {
                uint32_t off = (uint32_t)r * 128u + j * 16u;
                uint32_t swz = off ^ ((off >> 3) & 0x70);
                asm volatile("cp.async.cg.shared.global [%0], [%1], 16;"
                             :: "r"(dstb + swz), "l"(s4 + j * 16) : "memory");
            }
        } else {
#pragma unroll
            for (int j = 0; j < 8; j++)
                asm volatile("cp.async.cg.shared.global [%0], [%1], 16;"
                             :: "r"(dstb + (uint32_t)r * 128u + j * 16u), "l"(s4 + j * 16) : "memory");
        }
        asm volatile("cp.async.commit_group;" ::: "memory");
    };

    fill_kv(0);

    if (wid == 0) { TC_ALLOC(sb, 256); TC_RELINQ(); }
    if (tid == 0) { mbar_init(sb + 8, 1); mbar_init(sb + 16, 1); }
    __syncthreads();
    uint32_t tmem;
    asm volatile("ld.shared.b32 %0, [%1];" : "=r"(tmem) : "r"(sb));

    {
        int r = tid & 127, j0 = (tid >> 7) * 4;
        const uint4* s4 = (const uint4*)(g_qkv[0] + ((size_t)bh * SS + qt * 128 + r) * DH);
#pragma unroll
        for (int j = 0; j < 4; j++) {
            uint32_t off = (uint32_t)r * 128u + (j0 + j) * 16u;
            uint32_t swz = off ^ ((off >> 3) & 0x70);
            *(uint4*)(sm + SM_Q + swz) = s4[j0 + j];
        }
    }

    const uint32_t IDESC_S = (1u << 4) | (16u << 17) | (8u << 24);
    const uint32_t IDESC_O = (1u << 4) | (8u << 17)  | (8u << 24);
    int sph = 0, oph = 0;
    float lpart = 0.f;
    const int NKT = SS / 128;

    for (int kt = 0; kt < NKT; kt++) {
        if (kt > 0) { mbar_wait(sb + 16, (uint32_t)(oph & 1)); oph++; }
        asm volatile("cp.async.wait_group 0;" ::: "memory");
        asm volatile("fence.proxy.async.shared::cta;" ::: "memory");
        __syncthreads();

        if (wid == 0 && elect1()) {
            uint64_t dQ = mk_desc(sb + SM_Q);
            uint64_t dK = mk_desc(sb + SM_K);
#pragma unroll
            for (int ks = 0; ks < 4; ks++)
                mma_f16_ss(tmem, dQ + 2 * ks, dK + 2 * ks, IDESC_S, ks == 0 ? 0u : 1u);
            tc_commit(sb + 8);
        }

        {
            int d = tid & 63, shb = (tid >> 6) & 1, mh = tid >> 7;
            const unsigned short* vs = (const unsigned short*)(sm + SM_VST);
            char* vt = sm + SM_VT + shb * 8192;
#pragma unroll
            for (int i = 0; i < 16; i++) {
                int m = mh * 16 + i;
                int s0 = shb * 64 + 2 * m;
                uint32_t u = (uint32_t)vs[s0 * 64 + d] | ((uint32_t)vs[(s0 + 1) * 64 + d] << 16);
                uint32_t off = (uint32_t)d * 128u + m * 4u;
                uint32_t swz = off ^ ((off >> 3) & 0x70);
                *(uint32_t*)(vt + swz) = u;
            }
        }
        asm volatile("fence.proxy.async.shared::cta;" ::: "memory");
        __syncthreads();

        mbar_wait(sb + 8, (uint32_t)(sph & 1)); sph++;
        TC_FENCE_AFTER();

        if (kt + 1 < NKT) fill_kv(kt + 1);

        {
            int rw = wid & 3, cw = wid >> 2;
            uint32_t s0[32], s1[32];
            TC_LD_X32(s0, tmem + cw * 64);
            TC_LD_X32(s1, tmem + cw * 64 + 32);
            TC_WAIT_LD();
            TC_FENCE_BEFORE();
            int r = rw * 32 + lane;
            char* pb = sm + SM_P + cw * 16384;
#pragma unroll
            for (int m = 0; m < 32; m++) {
                int c0 = 2 * m, c1 = 2 * m + 1;
                float a = __uint_as_float(c0 < 32 ? s0[c0] : s1[c0 - 32]);
                float b = __uint_as_float(c1 < 32 ? s0[c1] : s1[c1 - 32]);
                float pa = __expf(a * 0.125f);
                float pbv = __expf(b * 0.125f);
                lpart += pa + pbv;
                uint32_t off = (uint32_t)r * 128u + m * 4u;
                uint32_t swz = off ^ ((off >> 3) & 0x70);
                *(uint32_t*)(pb + swz) = pack_h2(pa, pbv);
            }
        }
        asm volatile("fence.proxy.async.shared::cta;" ::: "memory");
        __syncthreads();

        if (wid == 0 && elect1()) {
#pragma unroll
            for (int kb = 0; kb < 2; kb++) {
                uint64_t dP = mk_desc(sb + SM_P + kb * 16384);
                uint64_t dV = mk_desc(sb + SM_VT + kb * 8192);
#pragma unroll
                for (int ks = 0; ks < 4; ks++) {
                    uint32_t en0 = (kt == 0 && kb == 0 && ks == 0) ? 0u : 1u;
                    mma_f16_ss(tmem + 128, dP + 2 * ks, dV + 2 * ks, IDESC_O, en0);
                }
            }
            tc_commit(sb + 16);
        }
    }
    mbar_wait(sb + 16, (uint32_t)(oph & 1)); oph++;
    TC_FENCE_AFTER();

    float* lred = (float*)(sm + SM_P);
    lred[tid] = lpart;
    __syncthreads();
    if (wid < 4) {
        uint32_t o0[32], o1[32];
        TC_LD_X32(o0, tmem + 128);
        TC_LD_X32(o1, tmem + 160);
        TC_WAIT_LD();
        TC_FENCE_BEFORE();
        int r = wid * 32 + lane;
        float inv = 1.f / (lred[r] + lred[r + 128]);
        int b = bh >> 4, h = bh & 15;
        int s = qt * 128 + r;
        uint32_t* ph = (uint32_t*)(outh + ((size_t)(b * SS + s)) * DD + h * 64);
#pragma unroll
        for (int m = 0; m < 32; m++) {
            int c0 = 2 * m, c1 = 2 * m + 1;
            float v0 = __uint_as_float(c0 < 32 ? o0[c0] : o1[c0 - 32]) * inv;
            float v1 = __uint_as_float(c1 < 32 ? o0[c1] : o1[c1 - 32]) * inv;
            ph[m] = pack_h2(v0, v1);
        }
    }
    __syncthreads();
    if (wid == 0) { TC_DEALLOC(tmem, 256); }

#else
    if (tid < 128) {
        int r = qt * 128 + tid;
        const fp16* Q = g_qkv[0] + ((size_t)bh * SS + r) * DH;
        float acc[DH];
        for (int d = 0; d < DH; d++) acc[d] = 0.f;
        float l = 0.f;
        for (int s = 0; s < SS; s++) {
            const fp16* Kp = g_qkv[1] + ((size_t)bh * SS + s) * DH;
            const fp16* Vp = g_qkv[2] + ((size_t)bh * SS + s) * DH;
            float sc = 0.f;
            for (int d = 0; d < DH; d++) sc += __half2float(Q[d]) * __half2float(Kp[d]);
            float p = expf(sc * 0.125f);
            l += p;
            for (int d = 0; d < DH; d++) acc[d] += p * __half2float(Vp[d]);
        }
        int b = bh >> 4, h = bh & 15;
        fp16* o = outh + ((size_t)(b * SS + r)) * DD + h * 64;
        for (int d = 0; d < DH; d++) o[d] = __float2half_rn(acc[d] / l);
    }
#endif
#endif
}

// ---------------- misc kernels ----------------
__global__ void zero_cnt_kernel() { if (threadIdx.x < NE) g_cnt[threadIdx.x] = 0; }

__global__ void loss_kernel(float* __restrict__ out, int out_size)
{
    int tid = threadIdx.x;
    __shared__ float red[256];
    __shared__ float sumsp[NE];
    __shared__ float sumz;
    float accp[NE];
#pragma unroll
    for (int e = 0; e < NE; e++) accp[e] = 0.f;
    float accz = 0.f;
    for (int t = tid; t < TT; t += 256) {
        float z = g_zz[t];
        accz += z * z;
#pragma unroll
        for (int e = 0; e < NE; e++) accp[e] += g_probs[t * NE + e];
    }
    red[tid] = accz; __syncthreads();
    for (int o = 128; o > 0; o >>= 1) { if (tid < o) red[tid] += red[tid + o]; __syncthreads(); }
    if (tid == 0) sumz = red[0];
    __syncthreads();
    for (int e = 0; e < NE; e++) {
        red[tid] = accp[e]; __syncthreads();
        for (int o = 128; o > 0; o >>= 1) { if (tid < o) red[tid] += red[tid + o]; __syncthreads(); }
        if (tid == 0) sumsp[e] = red[0];
        __syncthreads();
    }
    if (tid == 0) {
        float aux = 0.f;
        for (int e = 0; e < NE; e++)
            aux += ((float)g_cnt[e] / (float)TT) * (sumsp[e] / (float)TT);
        aux *= (float)NE / 2.f;
        float loss = aux + 0.001f * (sumz / (float)TT);
        for (int i = NMAIN; i < out_size; i++) out[i] = loss;
    }
}

__global__ void combine_kernel(float* __restrict__ out)
{
    int idx4 = (blockIdx.x * 256 + threadIdx.x) * 4;
    if (idx4 >= NMAIN) return;
    int t = idx4 >> 10, d = idx4 & 1023;
    int e0 = g_slot_e[2 * t], r0 = g_slot_r[2 * t];
    int e1 = g_slot_e[2 * t + 1], r1 = g_slot_r[2 * t + 1];
    float w0 = g_slot_w[2 * t], w1 = g_slot_w[2 * t + 1];
    float4 xv = *(const float4*)(g_x2 + idx4);
    uint2 y0u = *(const uint2*)(g_Y + ((size_t)e0 * TT + r0) * DD + d);
    uint2 y1u = *(const uint2*)(g_Y + ((size_t)e1 * TT + r1) * DD + d);
    __half2 a0 = *(__half2*)&y0u.x, a1 = *(__half2*)&y0u.y;
    __half2 b0 = *(__half2*)&y1u.x, b1 = *(__half2*)&y1u.y;
    float4 r;
    r.x = xv.x + w0 * __low2float(a0)  + w1 * __low2float(b0);
    r.y = xv.y + w0 * __high2float(a0) + w1 * __high2float(b0);
    r.z = xv.z + w0 * __low2float(a1)  + w1 * __low2float(b1);
    r.w = xv.w + w0 * __high2float(a1) + w1 * __high2float(b1);
    *(float4*)(out + idx4) = r;
}

// ---------------- launch ----------------
extern "C" void kernel_launch(void* const* d_in, const int* in_sizes, int n_in,
                              void* d_out, int out_size)
{
    const float* x   = (const float*)d_in[0];
    const float* ln1 = (const float*)d_in[1];
    const float* ln2 = (const float*)d_in[2];
    const float* wq  = (const float*)d_in[3];
    const float* wk  = (const float*)d_in[4];
    const float* wv  = (const float*)d_in[5];
    const float* wo  = (const float*)d_in[6];
    const float* wr  = (const float*)d_in[7];
    const float* w1  = (const float*)d_in[8];
    const float* w2  = (const float*)d_in[9];
    float* out = (float*)d_out;

    cudaFuncSetAttribute(tc_attn, cudaFuncAttributeMaxDynamicSharedMemorySize, ATT_SMEM);
    cudaFuncSetAttribute(tc_gemm<GM_QKV>,  cudaFuncAttributeMaxDynamicSharedMemorySize, G_SMEM);
    cudaFuncSetAttribute(tc_gemm<GM_RES>,  cudaFuncAttributeMaxDynamicSharedMemorySize, G_SMEM);
    cudaFuncSetAttribute(tc_gemm<GM_MOE1>, cudaFuncAttributeMaxDynamicSharedMemorySize, G_SMEM);
    cudaFuncSetAttribute(tc_gemm<GM_MOE2>, cudaFuncAttributeMaxDynamicSharedMemorySize, G_SMEM);

    fp16 *p_xn, *p_xn2, *p_ctx, *p_wpt, *p_w1t, *p_w2t, *p_H;
    float *p_x2;
    cudaGetSymbolAddress((void**)&p_xn,   g_xn);
    cudaGetSymbolAddress((void**)&p_xn2,  g_xn2);
    cudaGetSymbolAddress((void**)&p_ctx,  g_ctx);
    cudaGetSymbolAddress((void**)&p_x2,   g_x2);
    cudaGetSymbolAddress((void**)&p_wpt,  g_wpt);
    cudaGetSymbolAddress((void**)&p_w1t,  g_w1t);
    cudaGetSymbolAddress((void**)&p_w2t,  g_w2t);
    cudaGetSymbolAddress((void**)&p_H,    g_H);

    dim3 bt(256);
    // idx 0: fused wq/wk/wv convert
    wt_convert_qkv_kernel<<<dim3(DD/64, DD/64, 3), bt>>>(wq, wk, wv, p_wpt);
    // idx 1: rmsnorm 1
    rmsnorm_kernel<<<TT, 256>>>(x, ln1, p_xn);
    // idx 2: wo convert
    wt_convert_kernel<<<dim3(DD/64, DD/64, 1), bt>>>(wo, p_wpt + 3*DD*DD, DD, DD);
    // idx 3 (ncu -s 5 with observed offset ~2): QKV projections
    tc_gemm<GM_QKV><<<dim3(DD/256, TT/256, 3), 256, G_SMEM>>>(
        p_xn, p_wpt, nullptr, nullptr, nullptr, TT, DD, DD);

    wt_convert_kernel<<<dim3(FF/64, DD/64, NE), bt>>>(w1, p_w1t, DD, FF);
    wt_convert_kernel<<<dim3(DD/64, FF/64, NE), bt>>>(w2, p_w2t, FF, DD);

    tc_attn<<<dim3(BB * NH, SS / 128), 256, ATT_SMEM>>>(p_ctx);

    tc_gemm<GM_RES><<<dim3(DD/256, TT/256, 1), 256, G_SMEM>>>(
        p_ctx, p_wpt + 3*DD*DD, p_x2, x, nullptr, TT, DD, DD);

    zero_cnt_kernel<<<1, 32>>>();
    norm2_router_kernel<<<TT, 256>>>(p_x2, ln2, wr, p_xn2);
    loss_kernel<<<1, 256>>>(out, out_size);

    tc_gemm<GM_MOE1><<<dim3(FF/256, TT/256, NE), 256, G_SMEM>>>(
        p_xn2, p_w1t, nullptr, nullptr, p_H, TT, FF, DD);
    tc_gemm<GM_MOE2><<<dim3(DD/256, TT/256, NE), 256, G_SMEM>>>(
        p_H, p_w2t, nullptr, nullptr, nullptr, TT, DD, FF);

    combine_kernel<<<(NMAIN/4 + 255) / 256, 256>>>(out);
}

// round 16
// speedup vs baseline: 1.0862x; 1.0812x over previous
#include <cuda_runtime.h>
#include <cuda_fp16.h>
#include <math.h>
#include <stdint.h>

#define BB 2
#define SS 2048
#define DD 1024
#define NH 16
#define DH 64
#define NE 8
#define FF 4096
#define TT (BB*SS)
#define NMAIN (TT*DD)

typedef __half fp16;

__device__ fp16  g_xn[TT*DD];
__device__ fp16  g_xn2[TT*DD];
__device__ fp16  g_qkv[3][(size_t)TT*DD];
__device__ fp16  g_ctx[TT*DD];
__device__ float g_x2[TT*DD];
__device__ fp16  g_wpt[4*DD*DD];
__device__ fp16  g_w1t[(size_t)NE*DD*FF];
__device__ fp16  g_w2t[(size_t)NE*DD*FF];
__device__ fp16  g_H[(size_t)NE*TT*FF];
__device__ fp16  g_Y[(size_t)NE*TT*DD];
__device__ float g_probs[TT*NE];
__device__ float g_zz[TT];
__device__ int   g_cnt[NE];
__device__ int   g_rowlist[NE*TT];
__device__ int   g_slot_e[2*TT];
__device__ int   g_slot_r[2*TT];
__device__ float g_slot_w[2*TT];

__device__ __forceinline__ uint32_t smem_u32(const void* p) {
    uint32_t a;
    asm("{ .reg .u64 t; cvta.to.shared.u64 t, %1; cvt.u32.u64 %0, t; }" : "=r"(a) : "l"(p));
    return a;
}
__device__ __forceinline__ uint32_t elect1() {
    uint32_t p;
    asm volatile("{\n.reg .pred p;\nelect.sync _|p, 0xFFFFFFFF;\nselp.b32 %0, 1, 0, p;\n}" : "=r"(p));
    return p;
}
__device__ __forceinline__ void mbar_init(uint32_t a, uint32_t n) {
    asm volatile("mbarrier.init.shared.b64 [%0], %1;" :: "r"(a), "r"(n) : "memory");
}
__device__ __forceinline__ void mbar_wait(uint32_t a, uint32_t par) {
    asm volatile(
        "{\n.reg .pred P;\nLW%=:\n"
        "mbarrier.try_wait.parity.acquire.cta.shared::cta.b64 P, [%0], %1, 0x989680;\n"
        "@P bra LD%=;\nbra LW%=;\nLD%=:\n}" :: "r"(a), "r"(par) : "memory");
}
__device__ __forceinline__ uint64_t mk_desc(uint32_t addr) {
    return ((uint64_t)2 << 61) | ((uint64_t)1 << 46) | ((uint64_t)64 << 32)
         | ((uint64_t)1 << 16) | ((addr >> 4) & 0x3FFF);
}
__device__ __forceinline__ void tc_commit(uint32_t mbar) {
#if defined(__CUDA_ARCH_FEAT_SM103_ALL)
    asm volatile("tcgen05.commit.cta_group::1.mbarrier::arrive::one.shared::cluster.b64 [%0];"
                 :: "r"(mbar) : "memory");
#endif
}
__device__ __forceinline__ void mma_f16_ss(uint32_t d, uint64_t ad, uint64_t bd,
                                           uint32_t idesc, uint32_t en) {
#if defined(__CUDA_ARCH_FEAT_SM103_ALL)
    asm volatile(
        "{\n.reg .pred p;\nsetp.ne.u32 p, %4, 0;\n"
        "tcgen05.mma.cta_group::1.kind::f16 [%0], %1, %2, %3, {%5, %5, %5, %5}, p;\n}"
        :: "r"(d), "l"(ad), "l"(bd), "r"(idesc), "r"(en), "r"(0u) : "memory");
#endif
}

#if defined(__CUDA_ARCH_FEAT_SM103_ALL)
#define TC_ALLOC(sbaddr, n) \
    asm volatile("tcgen05.alloc.cta_group::1.sync.aligned.shared::cta.b32 [%0], %1;" \
                 :: "r"(sbaddr), "r"((uint32_t)(n)) : "memory")
#define TC_RELINQ() asm volatile("tcgen05.relinquish_alloc_permit.cta_group::1.sync.aligned;")
#define TC_DEALLOC(t, n) \
    asm volatile("tcgen05.dealloc.cta_group::1.sync.aligned.b32 %0, %1;" :: "r"(t), "r"((uint32_t)(n)))
#define TC_FENCE_AFTER()  asm volatile("tcgen05.fence::after_thread_sync;" ::: "memory")
#define TC_FENCE_BEFORE() asm volatile("tcgen05.fence::before_thread_sync;" ::: "memory")
#define TC_WAIT_LD()      asm volatile("tcgen05.wait::ld.sync.aligned;" ::: "memory")
#define TC_LD_X32(r, ta) \
    asm volatile( \
        "tcgen05.ld.sync.aligned.32x32b.x32.b32 " \
        "{%0, %1, %2, %3, %4, %5, %6, %7, %8, %9, %10, %11, %12, %13, %14, %15, " \
        " %16, %17, %18, %19, %20, %21, %22, %23, %24, %25, %26, %27, %28, %29, %30, %31}, [%32];" \
        : "=r"((r)[0]),  "=r"((r)[1]),  "=r"((r)[2]),  "=r"((r)[3]), \
          "=r"((r)[4]),  "=r"((r)[5]),  "=r"((r)[6]),  "=r"((r)[7]), \
          "=r"((r)[8]),  "=r"((r)[9]),  "=r"((r)[10]), "=r"((r)[11]), \
          "=r"((r)[12]), "=r"((r)[13]), "=r"((r)[14]), "=r"((r)[15]), \
          "=r"((r)[16]), "=r"((r)[17]), "=r"((r)[18]), "=r"((r)[19]), \
          "=r"((r)[20]), "=r"((r)[21]), "=r"((r)[22]), "=r"((r)[23]), \
          "=r"((r)[24]), "=r"((r)[25]), "=r"((r)[26]), "=r"((r)[27]), \
          "=r"((r)[28]), "=r"((r)[29]), "=r"((r)[30]), "=r"((r)[31]) \
        : "r"(ta))
#endif

__device__ __forceinline__ float gelu_tanh(float x) {
    float x3 = x * x * x;
    return 0.5f * x * (1.f + tanhf(0.7978845608028654f * (x + 0.044715f * x3)));
}
__device__ __forceinline__ uint32_t pack_h2(float a, float b) {
    __half2 h = __floats2half2_rn(a, b);
    return *(uint32_t*)&h;
}

// ---------------- rmsnorm 1 ----------------
__global__ void rmsnorm_kernel(const float* __restrict__ x, const float* __restrict__ w,
                               fp16* __restrict__ yh)
{
    int row = blockIdx.x, tid = threadIdx.x;
    int d4 = tid * 4;
    float4 xv = *(const float4*)(x + (size_t)row * DD + d4);
    float s = xv.x * xv.x + xv.y * xv.y + xv.z * xv.z + xv.w * xv.w;
    __shared__ float red[8];
    for (int o = 16; o > 0; o >>= 1) s += __shfl_xor_sync(0xffffffffu, s, o);
    if ((tid & 31) == 0) red[tid >> 5] = s;
    __syncthreads();
    float tot = 0.f;
#pragma unroll
    for (int i = 0; i < 8; i++) tot += red[i];
    float inv = rsqrtf(tot / (float)DD + 1e-6f);
    float4 wv = *(const float4*)(w + d4);
    uint2 p;
    p.x = pack_h2(xv.x * inv * wv.x, xv.y * inv * wv.y);
    p.y = pack_h2(xv.z * inv * wv.z, xv.w * inv * wv.w);
    *(uint2*)(yh + (size_t)row * DD + d4) = p;
}

// ---------------- fused rmsnorm2 + router ----------------
__global__ void norm2_router_kernel(const float* __restrict__ x2, const float* __restrict__ w,
                                    const float* __restrict__ wr, fp16* __restrict__ yh)
{
    int t = blockIdx.x, tid = threadIdx.x;
    int wid = tid >> 5, lane = tid & 31;
    int d4 = tid * 4;
    float4 xv = *(const float4*)(x2 + (size_t)t * DD + d4);
    float s = xv.x * xv.x + xv.y * xv.y + xv.z * xv.z + xv.w * xv.w;
    __shared__ float red[8];
    __shared__ float lp[8][NE];
    for (int o = 16; o > 0; o >>= 1) s += __shfl_xor_sync(0xffffffffu, s, o);
    if (lane == 0) red[wid] = s;
    __syncthreads();
    float tot = 0.f;
#pragma unroll
    for (int i = 0; i < 8; i++) tot += red[i];
    float inv = rsqrtf(tot / (float)DD + 1e-6f);
    float4 wv = *(const float4*)(w + d4);
    float v0 = xv.x * inv * wv.x, v1 = xv.y * inv * wv.y;
    float v2 = xv.z * inv * wv.z, v3 = xv.w * inv * wv.w;
    uint2 ph; ph.x = pack_h2(v0, v1); ph.y = pack_h2(v2, v3);
    *(uint2*)(yh + (size_t)t * DD + d4) = ph;
    float p[NE];
#pragma unroll
    for (int e = 0; e < NE; e++)
        p[e] = v0 * wr[(d4 + 0) * NE + e] + v1 * wr[(d4 + 1) * NE + e]
             + v2 * wr[(d4 + 2) * NE + e] + v3 * wr[(d4 + 3) * NE + e];
#pragma unroll
    for (int e = 0; e < NE; e++)
        for (int o = 16; o > 0; o >>= 1) p[e] += __shfl_xor_sync(0xffffffffu, p[e], o);
    if (lane == 0)
#pragma unroll
        for (int e = 0; e < NE; e++) lp[wid][e] = p[e];
    __syncthreads();
    if (tid == 0) {
        float lg[NE];
#pragma unroll
        for (int e = 0; e < NE; e++) {
            float a = 0.f;
#pragma unroll
            for (int wgi = 0; wgi < 8; wgi++) a += lp[wgi][e];
            lg[e] = a;
        }
        float m = lg[0];
#pragma unroll
        for (int e = 1; e < NE; e++) m = fmaxf(m, lg[e]);
        float pr[NE], sum = 0.f;
#pragma unroll
        for (int e = 0; e < NE; e++) { pr[e] = expf(lg[e] - m); sum += pr[e]; }
        float invs = 1.f / sum;
#pragma unroll
        for (int e = 0; e < NE; e++) pr[e] *= invs;
        g_zz[t] = m + logf(sum);
#pragma unroll
        for (int e = 0; e < NE; e++) g_probs[t * NE + e] = pr[e];
        int i0 = 0; float b0 = pr[0];
#pragma unroll
        for (int e = 1; e < NE; e++) if (pr[e] > b0) { b0 = pr[e]; i0 = e; }
        int i1 = -1; float b1 = -1.f;
#pragma unroll
        for (int e = 0; e < NE; e++) { if (e == i0) continue; if (pr[e] > b1) { b1 = pr[e]; i1 = e; } }
        float w0 = b0 / (b0 + b1), w1 = b1 / (b0 + b1);
        int r0 = atomicAdd(&g_cnt[i0], 1); g_rowlist[i0 * TT + r0] = t;
        int r1 = atomicAdd(&g_cnt[i1], 1); g_rowlist[i1 * TT + r1] = t;
        g_slot_e[2 * t]     = i0; g_slot_r[2 * t]     = r0; g_slot_w[2 * t]     = w0;
        g_slot_e[2 * t + 1] = i1; g_slot_r[2 * t + 1] = r1; g_slot_w[2 * t + 1] = w1;
    }
}

// ---------------- weight transpose -> fp16 (generic) -----------------------
__global__ void wt_convert_kernel(const float* __restrict__ W,
                                  fp16* __restrict__ Th, int K, int N)
{
    __shared__ float tile[64][68];
    size_t zoff = (size_t)blockIdx.z * K * N;
    int n0 = blockIdx.x * 64, k0 = blockIdx.y * 64;
    int tx = threadIdx.x & 15, ty = threadIdx.x >> 4;
#pragma unroll
    for (int i = 0; i < 4; i++) {
        int r = ty + 16 * i;
        *(float4*)&tile[r][tx * 4] = *(const float4*)(W + zoff + (size_t)(k0 + r) * N + n0 + tx * 4);
    }
    __syncthreads();
#pragma unroll
    for (int i = 0; i < 4; i++) {
        int n = ty + 16 * i, kk = tx * 4;
        size_t idx = zoff + (size_t)(n0 + n) * K + k0 + kk;
        *(uint2*)(Th + idx) = make_uint2(pack_h2(tile[kk][n], tile[kk + 1][n]),
                                         pack_h2(tile[kk + 2][n], tile[kk + 3][n]));
    }
}

// ---------------- fused wq/wk/wv transpose (z selects source) ---------------
__global__ void wt_convert_qkv_kernel(const float* __restrict__ Wq,
                                      const float* __restrict__ Wk,
                                      const float* __restrict__ Wv,
                                      fp16* __restrict__ Th)
{
    __shared__ float tile[64][68];
    const float* W = (blockIdx.z == 0) ? Wq : (blockIdx.z == 1 ? Wk : Wv);
    size_t zoff = (size_t)blockIdx.z * DD * DD;
    int n0 = blockIdx.x * 64, k0 = blockIdx.y * 64;
    int tx = threadIdx.x & 15, ty = threadIdx.x >> 4;
#pragma unroll
    for (int i = 0; i < 4; i++) {
        int r = ty + 16 * i;
        *(float4*)&tile[r][tx * 4] = *(const float4*)(W + (size_t)(k0 + r) * DD + n0 + tx * 4);
    }
    __syncthreads();
#pragma unroll
    for (int i = 0; i < 4; i++) {
        int n = ty + 16 * i, kk = tx * 4;
        size_t idx = zoff + (size_t)(n0 + n) * DD + k0 + kk;
        *(uint2*)(Th + idx) = make_uint2(pack_h2(tile[kk][n], tile[kk + 1][n]),
                                         pack_h2(tile[kk + 2][n], tile[kk + 3][n]));
    }
}

#define GM_QKV  1
#define GM_RES  2
#define GM_MOE1 3
#define GM_MOE2 4
#define BUF_BYTES 65536
#define G_SMEM  (1024 + 3 * BUF_BYTES)   // 197632, 3-stage pipeline, 1 CTA/SM

// ---------------- tcgen05 GEMM: C[256x256], fp16, 3-stage pipeline ---------
template<int MODE>
__global__ void __launch_bounds__(256, 1)
tc_gemm(const fp16* __restrict__ A, const fp16* __restrict__ B0,
        float* __restrict__ Cf, const float* __restrict__ Res,
        fp16* __restrict__ Ch, int M, int N, int K)
{
#if defined(__CUDA_ARCH__)
    extern __shared__ char sm[];
    int tid = threadIdx.x;
    int e  = blockIdx.z;
    int m0 = blockIdx.y * 256, n0 = blockIdx.x * 256;
    int Me = M;
    const fp16* B = B0;
    if (MODE == GM_MOE1 || MODE == GM_MOE2) {
        Me = g_cnt[e];
        if (m0 >= Me) return;
        B += (size_t)e * (size_t)K * N;
    } else if (MODE == GM_QKV) {
        B += (size_t)e * (size_t)K * N;
    }

#if defined(__CUDA_ARCH_FEAT_SM103_ALL)
    uint32_t sb = smem_u32(sm);
    int wid = tid >> 5, lid = tid & 31;
    int nk = K / 64;   // always >= 16 here

    auto issue_fill = [&](int kc, int bufi) {
        uint32_t tb = sb + 1024 + (uint32_t)bufi * BUF_BYTES;
#pragma unroll
        for (int it = 0; it < 2; it++) {
            int task = tid + it * 256;
            if (task < 256) {
                int gr = m0 + task;
                bool val = gr < Me;
                size_t ri = 0;
                if (val) {
                    if (MODE == GM_MOE1)      ri = (size_t)g_rowlist[e * TT + gr];
                    else if (MODE == GM_MOE2) ri = (size_t)e * TT + gr;
                    else                      ri = (size_t)gr;
                }
                const char* src = (const char*)(A + ri * (size_t)K + kc * 64);
                uint32_t sz = val ? 16u : 0u;
#pragma unroll
                for (int j = 0; j < 8; j++) {
                    uint32_t off = (uint32_t)task * 128u + j * 16u;
                    uint32_t swz = off ^ ((off >> 3) & 0x70);
                    asm volatile("cp.async.cg.shared.global [%0], [%1], 16, %2;"
                                 :: "r"(tb + swz), "l"(src + j * 16), "r"(sz) : "memory");
                }
            } else {
                int row = task - 256;
                const char* src = (const char*)(B + (size_t)(n0 + row) * K + kc * 64);
#pragma unroll
                for (int j = 0; j < 8; j++) {
                    uint32_t off = (uint32_t)row * 128u + j * 16u;
                    uint32_t swz = off ^ ((off >> 3) & 0x70);
                    asm volatile("cp.async.cg.shared.global [%0], [%1], 16;"
                                 :: "r"(tb + 32768 + swz), "l"(src + j * 16) : "memory");
                }
            }
        }
        asm volatile("cp.async.commit_group;" ::: "memory");
    };

    // prologue: fill 3 stages
    issue_fill(0, 0);
    issue_fill(1, 1);
    issue_fill(2, 2);

    if (wid == 0) { TC_ALLOC(sb, 512); TC_RELINQ(); }
    if (tid == 0) { mbar_init(sb + 8, 1); mbar_init(sb + 16, 1); mbar_init(sb + 24, 1); }
    __syncthreads();
    uint32_t tmem;
    asm volatile("ld.shared.b32 %0, [%1];" : "=r"(tmem) : "r"(sb));

    const uint32_t IDESC = (1u << 4) | (32u << 17) | (8u << 24);
    int ph0 = 0, ph1 = 0, ph2 = 0;
    for (int kc = 0; kc < nk; kc++) {
        int b = kc % 3;
        if (kc >= 2) {
            // MMA(kc-2) completed ~2 periods ago -> near-zero wait; frees buffer (kc+1)%3
            int wb = (kc - 2) % 3;
            if (wb == 0)      { mbar_wait(sb + 8,  (uint32_t)(ph0 & 1)); ph0++; }
            else if (wb == 1) { mbar_wait(sb + 16, (uint32_t)(ph1 & 1)); ph1++; }
            else              { mbar_wait(sb + 24, (uint32_t)(ph2 & 1)); ph2++; }
            if (kc + 1 < nk) issue_fill(kc + 1, (kc + 1) % 3);
        }
        if (kc == 0)              asm volatile("cp.async.wait_group 2;" ::: "memory");
        else if (kc + 1 < nk)     asm volatile("cp.async.wait_group 1;" ::: "memory");
        else                      asm volatile("cp.async.wait_group 0;" ::: "memory");
        asm volatile("fence.proxy.async.shared::cta;" ::: "memory");
        __syncthreads();
        if (wid == 0 && elect1()) {
            uint32_t tb = sb + 1024 + (uint32_t)b * BUF_BYTES;
            uint64_t dA0 = mk_desc(tb);
            uint64_t dA1 = mk_desc(tb + 16384);
            uint64_t dB  = mk_desc(tb + 32768);
#pragma unroll
            for (int s = 0; s < 4; s++) {
                uint32_t en0 = (kc == 0 && s == 0) ? 0u : 1u;
                mma_f16_ss(tmem,       dA0 + 2 * s, dB + 2 * s, IDESC, en0);
                mma_f16_ss(tmem + 256, dA1 + 2 * s, dB + 2 * s, IDESC, en0);
            }
            tc_commit(sb + 8 + b * 8);
        }
    }
    {
        // last commit tracks all prior MMAs
        int lb = (nk - 1) % 3;
        if (lb == 0)      mbar_wait(sb + 8,  (uint32_t)(ph0 & 1));
        else if (lb == 1) mbar_wait(sb + 16, (uint32_t)(ph1 & 1));
        else              mbar_wait(sb + 24, (uint32_t)(ph2 & 1));
    }
    TC_FENCE_AFTER();

    // staged coalesced epilogue: TMEM -> smem (128x129 fp32) -> contiguous global
    int rw = wid & 3, cw = wid >> 2;
    float* Cs = (float*)(sm + 1024);
#pragma unroll 1
    for (int rb = 0; rb < 2; rb++) {
        int mb = m0 + rb * 128;
        int rows_here = Me - mb;
        if (rows_here <= 0) break;
        if (rows_here > 128) rows_here = 128;
#pragma unroll 1
        for (int p = 0; p < 2; p++) {
            uint32_t d0[32], d1[32];
            TC_LD_X32(d0, tmem + rb * 256 + p * 128 + cw * 64);
            TC_LD_X32(d1, tmem + rb * 256 + p * 128 + cw * 64 + 32);
            TC_WAIT_LD();
            TC_FENCE_BEFORE();
            __syncthreads();
            {
                int rr = rw * 32 + lid, cb = cw * 64;
#pragma unroll
                for (int j = 0; j < 32; j++) {
                    Cs[rr * 129 + cb + j]      = __uint_as_float(d0[j]);
                    Cs[rr * 129 + cb + 32 + j] = __uint_as_float(d1[j]);
                }
            }
            __syncthreads();
#pragma unroll 4
            for (int it = 0; it < 16; it++) {
                int idx4 = (it * 256 + tid) * 4;
                int rr = idx4 >> 7, cc = idx4 & 127;
                if (rr >= rows_here) continue;
                float v0 = Cs[rr * 129 + cc + 0], v1 = Cs[rr * 129 + cc + 1];
                float v2 = Cs[rr * 129 + cc + 2], v3 = Cs[rr * 129 + cc + 3];
                int colb = n0 + p * 128 + cc;
                if (MODE == GM_RES) {
                    size_t o = (size_t)(mb + rr) * N + colb;
                    float4 rs = *(const float4*)(Res + o);
                    *(float4*)(Cf + o) = make_float4(v0 + rs.x, v1 + rs.y, v2 + rs.z, v3 + rs.w);
                } else if (MODE == GM_MOE2) {
                    size_t o = ((size_t)e * TT + mb + rr) * N + colb;
                    uint2 ph; ph.x = pack_h2(v0, v1); ph.y = pack_h2(v2, v3);
                    *(uint2*)(g_Y + o) = ph;
                } else if (MODE == GM_MOE1) {
                    size_t o = ((size_t)e * TT + mb + rr) * N + colb;
                    uint2 ph;
                    ph.x = pack_h2(gelu_tanh(v0), gelu_tanh(v1));
                    ph.y = pack_h2(gelu_tanh(v2), gelu_tanh(v3));
                    *(uint2*)(Ch + o) = ph;
                } else {
                    int row = mb + rr;
                    int b2 = row >> 11, s5 = row & (SS - 1);
                    int h = colb >> 6, dh = colb & 63;
                    size_t o = (((size_t)(b2 * NH + h)) * SS + s5) * DH + dh;
                    uint2 ph; ph.x = pack_h2(v0, v1); ph.y = pack_h2(v2, v3);
                    *(uint2*)(g_qkv[e] + o) = ph;
                }
            }
            __syncthreads();
        }
    }
    if (wid == 0) { TC_DEALLOC(tmem, 512); }

#else
    // compact SIMT fallback (never runs when sm_103a SASS is loaded)
    for (int i = tid; i < 256 * 256; i += 256) {
        int rr = i >> 8, cc = i & 255;
        int row = m0 + rr;
        if (row >= Me) continue;
        size_t ri;
        if (MODE == GM_MOE1)      ri = (size_t)g_rowlist[e * TT + row];
        else if (MODE == GM_MOE2) ri = (size_t)e * TT + row;
        else                      ri = (size_t)row;
        float acc = 0.f;
        const fp16* ar = A + ri * (size_t)K;
        const fp16* br = B + (size_t)(n0 + cc) * K;
        for (int k = 0; k < K; k++)
            acc += __half2float(ar[k]) * __half2float(br[k]);
        if (MODE == GM_RES) { size_t o = (size_t)row * N + n0 + cc; Cf[o] = acc + Res[o]; }
        else if (MODE == GM_MOE2) g_Y[((size_t)e * TT + row) * N + n0 + cc] = __float2half_rn(acc);
        else if (MODE == GM_MOE1) Ch[((size_t)e * TT + row) * N + n0 + cc] = __float2half_rn(gelu_tanh(acc));
        else {
            int col = n0 + cc, b2 = row >> 11, s5 = row & (SS - 1);
            g_qkv[e][(((size_t)(b2 * NH + (col >> 6))) * SS + s5) * DH + (col & 63)] = __float2half_rn(acc);
        }
    }
#endif
#endif
}

// ---------------- tcgen05 flash attention (unchanged) ----------------------
#define SM_Q   1024
#define SM_K   17408
#define SM_VST 33792
#define SM_VT  50176
#define SM_P   66560
#define ATT_SMEM 100352

__global__ void __launch_bounds__(256, 2)
tc_attn(fp16* __restrict__ outh)
{
#if defined(__CUDA_ARCH__)
    extern __shared__ char sm[];
    int tid = threadIdx.x;
    int bh = blockIdx.x;
    int qt = blockIdx.y;

#if defined(__CUDA_ARCH_FEAT_SM103_ALL)
    uint32_t sb = smem_u32(sm);
    int wid = tid >> 5, lane = tid & 31;

    auto fill_kv = [&](int kt) {
        int arr = tid >> 7, r = tid & 127;
        const fp16* src = (arr == 0 ? g_qkv[1] : g_qkv[2]);
        uint32_t dstb = (arr == 0 ? sb + SM_K : sb + SM_VST);
        const char* s4 = (const char*)(src + ((size_t)bh * SS + kt * 128 + r) * DH);
        if (arr == 0) {
#pragma unroll
            for (int j = 0; j < 8; j++) {
                uint32_t off = (uint32_t)r * 128u + j * 16u;
                uint32_t swz = off ^ ((off >> 3) & 0x70);
                asm volatile("cp.async.cg.shared.global [%0], [%1], 16;"
                             :: "r"(dstb + swz), "l"(s4 + j * 16) : "memory");
            }
        } else {
#pragma unroll
            for (int j = 0; j < 8; j++)
                asm volatile("cp.async.cg.shared.global [%0], [%1], 16;"
                             :: "r"(dstb + (uint32_t)r * 128u + j * 16u), "l"(s4 + j * 16) : "memory");
        }
        asm volatile("cp.async.commit_group;" ::: "memory");
    };

    fill_kv(0);

    if (wid == 0) { TC_ALLOC(sb, 256); TC_RELINQ(); }
    if (tid == 0) { mbar_init(sb + 8, 1); mbar_init(sb + 16, 1); }
    __syncthreads();
    uint32_t tmem;
    asm volatile("ld.shared.b32 %0, [%1];" : "=r"(tmem) : "r"(sb));

    {
        int r = tid & 127, j0 = (tid >> 7) * 4;
        const uint4* s4 = (const uint4*)(g_qkv[0] + ((size_t)bh * SS + qt * 128 + r) * DH);
#pragma unroll
        for (int j = 0; j < 4; j++) {
            uint32_t off = (uint32_t)r * 128u + (j0 + j) * 16u;
            uint32_t swz = off ^ ((off >> 3) & 0x70);
            *(uint4*)(sm + SM_Q + swz) = s4[j0 + j];
        }
    }

    const uint32_t IDESC_S = (1u << 4) | (16u << 17) | (8u << 24);
    const uint32_t IDESC_O = (1u << 4) | (8u << 17)  | (8u << 24);
    int sph = 0, oph = 0;
    float lpart = 0.f;
    const int NKT = SS / 128;

    for (int kt = 0; kt < NKT; kt++) {
        if (kt > 0) { mbar_wait(sb + 16, (uint32_t)(oph & 1)); oph++; }
        asm volatile("cp.async.wait_group 0;" ::: "memory");
        asm volatile("fence.proxy.async.shared::cta;" ::: "memory");
        __syncthreads();

        if (wid == 0 && elect1()) {
            uint64_t dQ = mk_desc(sb + SM_Q);
            uint64_t dK = mk_desc(sb + SM_K);
#pragma unroll
            for (int ks = 0; ks < 4; ks++)
                mma_f16_ss(tmem, dQ + 2 * ks, dK + 2 * ks, IDESC_S, ks == 0 ? 0u : 1u);
            tc_commit(sb + 8);
        }

        {
            int d = tid & 63, shb = (tid >> 6) & 1, mh = tid >> 7;
            const unsigned short* vs = (const unsigned short*)(sm + SM_VST);
            char* vt = sm + SM_VT + shb * 8192;
#pragma unroll
            for (int i = 0; i < 16; i++) {
                int m = mh * 16 + i;
                int s0 = shb * 64 + 2 * m;
                uint32_t u = (uint32_t)vs[s0 * 64 + d] | ((uint32_t)vs[(s0 + 1) * 64 + d] << 16);
                uint32_t off = (uint32_t)d * 128u + m * 4u;
                uint32_t swz = off ^ ((off >> 3) & 0x70);
                *(uint32_t*)(vt + swz) = u;
            }
        }
        asm volatile("fence.proxy.async.shared::cta;" ::: "memory");
        __syncthreads();

        mbar_wait(sb + 8, (uint32_t)(sph & 1)); sph++;
        TC_FENCE_AFTER();

        if (kt + 1 < NKT) fill_kv(kt + 1);

        {
            int rw = wid & 3, cw = wid >> 2;
            uint32_t s0[32], s1[32];
            TC_LD_X32(s0, tmem + cw * 64);
            TC_LD_X32(s1, tmem + cw * 64 + 32);
            TC_WAIT_LD();
            TC_FENCE_BEFORE();
            int r = rw * 32 + lane;
            char* pb = sm + SM_P + cw * 16384;
#pragma unroll
            for (int m = 0; m < 32; m++) {
                int c0 = 2 * m, c1 = 2 * m + 1;
                float a = __uint_as_float(c0 < 32 ? s0[c0] : s1[c0 - 32]);
                float b = __uint_as_float(c1 < 32 ? s0[c1] : s1[c1 - 32]);
                float pa = __expf(a * 0.125f);
                float pbv = __expf(b * 0.125f);
                lpart += pa + pbv;
                uint32_t off = (uint32_t)r * 128u + m * 4u;
                uint32_t swz = off ^ ((off >> 3) & 0x70);
                *(uint32_t*)(pb + swz) = pack_h2(pa, pbv);
            }
        }
        asm volatile("fence.proxy.async.shared::cta;" ::: "memory");
        __syncthreads();

        if (wid == 0 && elect1()) {
#pragma unroll
            for (int kb = 0; kb < 2; kb++) {
                uint64_t dP = mk_desc(sb + SM_P + kb * 16384);
                uint64_t dV = mk_desc(sb + SM_VT + kb * 8192);
#pragma unroll
                for (int ks = 0; ks < 4; ks++) {
                    uint32_t en0 = (kt == 0 && kb == 0 && ks == 0) ? 0u : 1u;
                    mma_f16_ss(tmem + 128, dP + 2 * ks, dV + 2 * ks, IDESC_O, en0);
                }
            }
            tc_commit(sb + 16);
        }
    }
    mbar_wait(sb + 16, (uint32_t)(oph & 1)); oph++;
    TC_FENCE_AFTER();

    float* lred = (float*)(sm + SM_P);
    lred[tid] = lpart;
    __syncthreads();
    if (wid < 4) {
        uint32_t o0[32], o1[32];
        TC_LD_X32(o0, tmem + 128);
        TC_LD_X32(o1, tmem + 160);
        TC_WAIT_LD();
        TC_FENCE_BEFORE();
        int r = wid * 32 + lane;
        float inv = 1.f / (lred[r] + lred[r + 128]);
        int b = bh >> 4, h = bh & 15;
        int s = qt * 128 + r;
        uint32_t* ph = (uint32_t*)(outh + ((size_t)(b * SS + s)) * DD + h * 64);
#pragma unroll
        for (int m = 0; m < 32; m++) {
            int c0 = 2 * m, c1 = 2 * m + 1;
            float v0 = __uint_as_float(c0 < 32 ? o0[c0] : o1[c0 - 32]) * inv;
            float v1 = __uint_as_float(c1 < 32 ? o0[c1] : o1[c1 - 32]) * inv;
            ph[m] = pack_h2(v0, v1);
        }
    }
    __syncthreads();
    if (wid == 0) { TC_DEALLOC(tmem, 256); }

#else
    if (tid < 128) {
        int r = qt * 128 + tid;
        const fp16* Q = g_qkv[0] + ((size_t)bh * SS + r) * DH;
        float acc[DH];
        for (int d = 0; d < DH; d++) acc[d] = 0.f;
        float l = 0.f;
        for (int s = 0; s < SS; s++) {
            const fp16* Kp = g_qkv[1] + ((size_t)bh * SS + s) * DH;
            const fp16* Vp = g_qkv[2] + ((size_t)bh * SS + s) * DH;
            float sc = 0.f;
            for (int d = 0; d < DH; d++) sc += __half2float(Q[d]) * __half2float(Kp[d]);
            float p = expf(sc * 0.125f);
            l += p;
            for (int d = 0; d < DH; d++) acc[d] += p * __half2float(Vp[d]);
        }
        int b = bh >> 4, h = bh & 15;
        fp16* o = outh + ((size_t)(b * SS + r)) * DD + h * 64;
        for (int d = 0; d < DH; d++) o[d] = __float2half_rn(acc[d] / l);
    }
#endif
#endif
}

// ---------------- misc kernels ----------------
__global__ void zero_cnt_kernel() { if (threadIdx.x < NE) g_cnt[threadIdx.x] = 0; }

__global__ void loss_kernel(float* __restrict__ out, int out_size)
{
    int tid = threadIdx.x;
    __shared__ float red[256];
    __shared__ float sumsp[NE];
    __shared__ float sumz;
    float accp[NE];
#pragma unroll
    for (int e = 0; e < NE; e++) accp[e] = 0.f;
    float accz = 0.f;
    for (int t = tid; t < TT; t += 256) {
        float z = g_zz[t];
        accz += z * z;
#pragma unroll
        for (int e = 0; e < NE; e++) accp[e] += g_probs[t * NE + e];
    }
    red[tid] = accz; __syncthreads();
    for (int o = 128; o > 0; o >>= 1) { if (tid < o) red[tid] += red[tid + o]; __syncthreads(); }
    if (tid == 0) sumz = red[0];
    __syncthreads();
    for (int e = 0; e < NE; e++) {
        red[tid] = accp[e]; __syncthreads();
        for (int o = 128; o > 0; o >>= 1) { if (tid < o) red[tid] += red[tid + o]; __syncthreads(); }
        if (tid == 0) sumsp[e] = red[0];
        __syncthreads();
    }
    if (tid == 0) {
        float aux = 0.f;
        for (int e = 0; e < NE; e++)
            aux += ((float)g_cnt[e] / (float)TT) * (sumsp[e] / (float)TT);
        aux *= (float)NE / 2.f;
        float loss = aux + 0.001f * (sumz / (float)TT);
        for (int i = NMAIN; i < out_size; i++) out[i] = loss;
    }
}

__global__ void combine_kernel(float* __restrict__ out)
{
    int idx4 = (blockIdx.x * 256 + threadIdx.x) * 4;
    if (idx4 >= NMAIN) return;
    int t = idx4 >> 10, d = idx4 & 1023;
    int e0 = g_slot_e[2 * t], r0 = g_slot_r[2 * t];
    int e1 = g_slot_e[2 * t + 1], r1 = g_slot_r[2 * t + 1];
    float w0 = g_slot_w[2 * t], w1 = g_slot_w[2 * t + 1];
    float4 xv = *(const float4*)(g_x2 + idx4);
    uint2 y0u = *(const uint2*)(g_Y + ((size_t)e0 * TT + r0) * DD + d);
    uint2 y1u = *(const uint2*)(g_Y + ((size_t)e1 * TT + r1) * DD + d);
    __half2 a0 = *(__half2*)&y0u.x, a1 = *(__half2*)&y0u.y;
    __half2 b0 = *(__half2*)&y1u.x, b1 = *(__half2*)&y1u.y;
    float4 r;
    r.x = xv.x + w0 * __low2float(a0)  + w1 * __low2float(b0);
    r.y = xv.y + w0 * __high2float(a0) + w1 * __high2float(b0);
    r.z = xv.z + w0 * __low2float(a1)  + w1 * __low2float(b1);
    r.w = xv.w + w0 * __high2float(a1) + w1 * __high2float(b1);
    *(float4*)(out + idx4) = r;
}

// ---------------- launch ----------------
extern "C" void kernel_launch(void* const* d_in, const int* in_sizes, int n_in,
                              void* d_out, int out_size)
{
    const float* x   = (const float*)d_in[0];
    const float* ln1 = (const float*)d_in[1];
    const float* ln2 = (const float*)d_in[2];
    const float* wq  = (const float*)d_in[3];
    const float* wk  = (const float*)d_in[4];
    const float* wv  = (const float*)d_in[5];
    const float* wo  = (const float*)d_in[6];
    const float* wr  = (const float*)d_in[7];
    const float* w1  = (const float*)d_in[8];
    const float* w2  = (const float*)d_in[9];
    float* out = (float*)d_out;

    cudaFuncSetAttribute(tc_attn, cudaFuncAttributeMaxDynamicSharedMemorySize, ATT_SMEM);
    cudaFuncSetAttribute(tc_gemm<GM_QKV>,  cudaFuncAttributeMaxDynamicSharedMemorySize, G_SMEM);
    cudaFuncSetAttribute(tc_gemm<GM_RES>,  cudaFuncAttributeMaxDynamicSharedMemorySize, G_SMEM);
    cudaFuncSetAttribute(tc_gemm<GM_MOE1>, cudaFuncAttributeMaxDynamicSharedMemorySize, G_SMEM);
    cudaFuncSetAttribute(tc_gemm<GM_MOE2>, cudaFuncAttributeMaxDynamicSharedMemorySize, G_SMEM);

    fp16 *p_xn, *p_xn2, *p_ctx, *p_wpt, *p_w1t, *p_w2t, *p_H;
    float *p_x2;
    cudaGetSymbolAddress((void**)&p_xn,   g_xn);
    cudaGetSymbolAddress((void**)&p_xn2,  g_xn2);
    cudaGetSymbolAddress((void**)&p_ctx,  g_ctx);
    cudaGetSymbolAddress((void**)&p_x2,   g_x2);
    cudaGetSymbolAddress((void**)&p_wpt,  g_wpt);
    cudaGetSymbolAddress((void**)&p_w1t,  g_w1t);
    cudaGetSymbolAddress((void**)&p_w2t,  g_w2t);
    cudaGetSymbolAddress((void**)&p_H,    g_H);

    dim3 bt(256);
    // idx 0: fused wq/wk/wv convert
    wt_convert_qkv_kernel<<<dim3(DD/64, DD/64, 3), bt>>>(wq, wk, wv, p_wpt);
    // idx 1: rmsnorm 1
    rmsnorm_kernel<<<TT, 256>>>(x, ln1, p_xn);
    // idx 2: wo convert
    wt_convert_kernel<<<dim3(DD/64, DD/64, 1), bt>>>(wo, p_wpt + 3*DD*DD, DD, DD);
    // idx 3 (ncu slot): QKV projections
    tc_gemm<GM_QKV><<<dim3(DD/256, TT/256, 3), 256, G_SMEM>>>(
        p_xn, p_wpt, nullptr, nullptr, nullptr, TT, DD, DD);

    wt_convert_kernel<<<dim3(FF/64, DD/64, NE), bt>>>(w1, p_w1t, DD, FF);
    wt_convert_kernel<<<dim3(DD/64, FF/64, NE), bt>>>(w2, p_w2t, FF, DD);

    tc_attn<<<dim3(BB * NH, SS / 128), 256, ATT_SMEM>>>(p_ctx);

    tc_gemm<GM_RES><<<dim3(DD/256, TT/256, 1), 256, G_SMEM>>>(
        p_ctx, p_wpt + 3*DD*DD, p_x2, x, nullptr, TT, DD, DD);

    zero_cnt_kernel<<<1, 32>>>();
    norm2_router_kernel<<<TT, 256>>>(p_x2, ln2, wr, p_xn2);
    loss_kernel<<<1, 256>>>(out, out_size);

    tc_gemm<GM_MOE1><<<dim3(FF/256, TT/256, NE), 256, G_SMEM>>>(
        p_xn2, p_w1t, nullptr, nullptr, p_H, TT, FF, DD);
    tc_gemm<GM_MOE2><<<dim3(DD/256, TT/256, NE), 256, G_SMEM>>>(
        p_H, p_w2t, nullptr, nullptr, nullptr, TT, DD, FF);

    combine_kernel<<<(NMAIN/4 + 255) / 256, 256>>>(out);
}

// round 17
// speedup vs baseline: 1.1296x; 1.0400x over previous
#include <cuda_runtime.h>
#include <cuda_fp16.h>
#include <math.h>
#include <stdint.h>

#define BB 2
#define SS 2048
#define DD 1024
#define NH 16
#define DH 64
#define NE 8
#define FF 4096
#define TT (BB*SS)
#define NMAIN (TT*DD)

typedef __half fp16;

__device__ fp16  g_xn[TT*DD];
__device__ fp16  g_xn2[TT*DD];
__device__ fp16  g_qkv[3][(size_t)TT*DD];
__device__ fp16  g_ctx[TT*DD];
__device__ float g_x2[TT*DD];
__device__ fp16  g_wpt[4*DD*DD];
__device__ fp16  g_w1t[(size_t)NE*DD*FF];
__device__ fp16  g_w2t[(size_t)NE*DD*FF];
__device__ fp16  g_H[(size_t)NE*TT*FF];
__device__ fp16  g_Y[(size_t)NE*TT*DD];
__device__ float g_probs[TT*NE];
__device__ float g_zz[TT];
__device__ int   g_cnt[NE];
__device__ int   g_rowlist[NE*TT];
__device__ int   g_slot_e[2*TT];
__device__ int   g_slot_r[2*TT];
__device__ float g_slot_w[2*TT];

__device__ __forceinline__ uint32_t smem_u32(const void* p) {
    uint32_t a;
    asm("{ .reg .u64 t; cvta.to.shared.u64 t, %1; cvt.u32.u64 %0, t; }" : "=r"(a) : "l"(p));
    return a;
}
__device__ __forceinline__ uint32_t elect1() {
    uint32_t p;
    asm volatile("{\n.reg .pred p;\nelect.sync _|p, 0xFFFFFFFF;\nselp.b32 %0, 1, 0, p;\n}" : "=r"(p));
    return p;
}
__device__ __forceinline__ void mbar_init(uint32_t a, uint32_t n) {
    asm volatile("mbarrier.init.shared.b64 [%0], %1;" :: "r"(a), "r"(n) : "memory");
}
__device__ __forceinline__ void mbar_wait(uint32_t a, uint32_t par) {
    asm volatile(
        "{\n.reg .pred P;\nLW%=:\n"
        "mbarrier.try_wait.parity.acquire.cta.shared::cta.b64 P, [%0], %1, 0x989680;\n"
        "@P bra LD%=;\nbra LW%=;\nLD%=:\n}" :: "r"(a), "r"(par) : "memory");
}
__device__ __forceinline__ uint64_t mk_desc(uint32_t addr) {
    return ((uint64_t)2 << 61) | ((uint64_t)1 << 46) | ((uint64_t)64 << 32)
         | ((uint64_t)1 << 16) | ((addr >> 4) & 0x3FFF);
}
__device__ __forceinline__ void tc_commit(uint32_t mbar) {
#if defined(__CUDA_ARCH_FEAT_SM103_ALL)
    asm volatile("tcgen05.commit.cta_group::1.mbarrier::arrive::one.shared::cluster.b64 [%0];"
                 :: "r"(mbar) : "memory");
#endif
}
__device__ __forceinline__ void mma_f16_ss(uint32_t d, uint64_t ad, uint64_t bd,
                                           uint32_t idesc, uint32_t en) {
#if defined(__CUDA_ARCH_FEAT_SM103_ALL)
    asm volatile(
        "{\n.reg .pred p;\nsetp.ne.u32 p, %4, 0;\n"
        "tcgen05.mma.cta_group::1.kind::f16 [%0], %1, %2, %3, {%5, %5, %5, %5}, p;\n}"
        :: "r"(d), "l"(ad), "l"(bd), "r"(idesc), "r"(en), "r"(0u) : "memory");
#endif
}

#if defined(__CUDA_ARCH_FEAT_SM103_ALL)
#define TC_ALLOC(sbaddr, n) \
    asm volatile("tcgen05.alloc.cta_group::1.sync.aligned.shared::cta.b32 [%0], %1;" \
                 :: "r"(sbaddr), "r"((uint32_t)(n)) : "memory")
#define TC_RELINQ() asm volatile("tcgen05.relinquish_alloc_permit.cta_group::1.sync.aligned;")
#define TC_DEALLOC(t, n) \
    asm volatile("tcgen05.dealloc.cta_group::1.sync.aligned.b32 %0, %1;" :: "r"(t), "r"((uint32_t)(n)))
#define TC_FENCE_AFTER()  asm volatile("tcgen05.fence::after_thread_sync;" ::: "memory")
#define TC_FENCE_BEFORE() asm volatile("tcgen05.fence::before_thread_sync;" ::: "memory")
#define TC_WAIT_LD()      asm volatile("tcgen05.wait::ld.sync.aligned;" ::: "memory")
#define TC_LD_X32(r, ta) \
    asm volatile( \
        "tcgen05.ld.sync.aligned.32x32b.x32.b32 " \
        "{%0, %1, %2, %3, %4, %5, %6, %7, %8, %9, %10, %11, %12, %13, %14, %15, " \
        " %16, %17, %18, %19, %20, %21, %22, %23, %24, %25, %26, %27, %28, %29, %30, %31}, [%32];" \
        : "=r"((r)[0]),  "=r"((r)[1]),  "=r"((r)[2]),  "=r"((r)[3]), \
          "=r"((r)[4]),  "=r"((r)[5]),  "=r"((r)[6]),  "=r"((r)[7]), \
          "=r"((r)[8]),  "=r"((r)[9]),  "=r"((r)[10]), "=r"((r)[11]), \
          "=r"((r)[12]), "=r"((r)[13]), "=r"((r)[14]), "=r"((r)[15]), \
          "=r"((r)[16]), "=r"((r)[17]), "=r"((r)[18]), "=r"((r)[19]), \
          "=r"((r)[20]), "=r"((r)[21]), "=r"((r)[22]), "=r"((r)[23]), \
          "=r"((r)[24]), "=r"((r)[25]), "=r"((r)[26]), "=r"((r)[27]), \
          "=r"((r)[28]), "=r"((r)[29]), "=r"((r)[30]), "=r"((r)[31]) \
        : "r"(ta))
#endif

__device__ __forceinline__ float gelu_tanh(float x) {
    float x3 = x * x * x;
    return 0.5f * x * (1.f + tanhf(0.7978845608028654f * (x + 0.044715f * x3)));
}
__device__ __forceinline__ uint32_t pack_h2(float a, float b) {
    __half2 h = __floats2half2_rn(a, b);
    return *(uint32_t*)&h;
}

// ---------------- rmsnorm 1 ----------------
__global__ void rmsnorm_kernel(const float* __restrict__ x, const float* __restrict__ w,
                               fp16* __restrict__ yh)
{
    int row = blockIdx.x, tid = threadIdx.x;
    int d4 = tid * 4;
    float4 xv = *(const float4*)(x + (size_t)row * DD + d4);
    float s = xv.x * xv.x + xv.y * xv.y + xv.z * xv.z + xv.w * xv.w;
    __shared__ float red[8];
    for (int o = 16; o > 0; o >>= 1) s += __shfl_xor_sync(0xffffffffu, s, o);
    if ((tid & 31) == 0) red[tid >> 5] = s;
    __syncthreads();
    float tot = 0.f;
#pragma unroll
    for (int i = 0; i < 8; i++) tot += red[i];
    float inv = rsqrtf(tot / (float)DD + 1e-6f);
    float4 wv = *(const float4*)(w + d4);
    uint2 p;
    p.x = pack_h2(xv.x * inv * wv.x, xv.y * inv * wv.y);
    p.y = pack_h2(xv.z * inv * wv.z, xv.w * inv * wv.w);
    *(uint2*)(yh + (size_t)row * DD + d4) = p;
}

// ---------------- fused rmsnorm2 + router ----------------
__global__ void norm2_router_kernel(const float* __restrict__ x2, const float* __restrict__ w,
                                    const float* __restrict__ wr, fp16* __restrict__ yh)
{
    int t = blockIdx.x, tid = threadIdx.x;
    int wid = tid >> 5, lane = tid & 31;
    int d4 = tid * 4;
    float4 xv = *(const float4*)(x2 + (size_t)t * DD + d4);
    float s = xv.x * xv.x + xv.y * xv.y + xv.z * xv.z + xv.w * xv.w;
    __shared__ float red[8];
    __shared__ float lp[8][NE];
    for (int o = 16; o > 0; o >>= 1) s += __shfl_xor_sync(0xffffffffu, s, o);
    if (lane == 0) red[wid] = s;
    __syncthreads();
    float tot = 0.f;
#pragma unroll
    for (int i = 0; i < 8; i++) tot += red[i];
    float inv = rsqrtf(tot / (float)DD + 1e-6f);
    float4 wv = *(const float4*)(w + d4);
    float v0 = xv.x * inv * wv.x, v1 = xv.y * inv * wv.y;
    float v2 = xv.z * inv * wv.z, v3 = xv.w * inv * wv.w;
    uint2 ph; ph.x = pack_h2(v0, v1); ph.y = pack_h2(v2, v3);
    *(uint2*)(yh + (size_t)t * DD + d4) = ph;
    float p[NE];
#pragma unroll
    for (int e = 0; e < NE; e++)
        p[e] = v0 * wr[(d4 + 0) * NE + e] + v1 * wr[(d4 + 1) * NE + e]
             + v2 * wr[(d4 + 2) * NE + e] + v3 * wr[(d4 + 3) * NE + e];
#pragma unroll
    for (int e = 0; e < NE; e++)
        for (int o = 16; o > 0; o >>= 1) p[e] += __shfl_xor_sync(0xffffffffu, p[e], o);
    if (lane == 0)
#pragma unroll
        for (int e = 0; e < NE; e++) lp[wid][e] = p[e];
    __syncthreads();
    if (tid == 0) {
        float lg[NE];
#pragma unroll
        for (int e = 0; e < NE; e++) {
            float a = 0.f;
#pragma unroll
            for (int wgi = 0; wgi < 8; wgi++) a += lp[wgi][e];
            lg[e] = a;
        }
        float m = lg[0];
#pragma unroll
        for (int e = 1; e < NE; e++) m = fmaxf(m, lg[e]);
        float pr[NE], sum = 0.f;
#pragma unroll
        for (int e = 0; e < NE; e++) { pr[e] = expf(lg[e] - m); sum += pr[e]; }
        float invs = 1.f / sum;
#pragma unroll
        for (int e = 0; e < NE; e++) pr[e] *= invs;
        g_zz[t] = m + logf(sum);
#pragma unroll
        for (int e = 0; e < NE; e++) g_probs[t * NE + e] = pr[e];
        int i0 = 0; float b0 = pr[0];
#pragma unroll
        for (int e = 1; e < NE; e++) if (pr[e] > b0) { b0 = pr[e]; i0 = e; }
        int i1 = -1; float b1 = -1.f;
#pragma unroll
        for (int e = 0; e < NE; e++) { if (e == i0) continue; if (pr[e] > b1) { b1 = pr[e]; i1 = e; } }
        float w0 = b0 / (b0 + b1), w1 = b1 / (b0 + b1);
        int r0 = atomicAdd(&g_cnt[i0], 1); g_rowlist[i0 * TT + r0] = t;
        int r1 = atomicAdd(&g_cnt[i1], 1); g_rowlist[i1 * TT + r1] = t;
        g_slot_e[2 * t]     = i0; g_slot_r[2 * t]     = r0; g_slot_w[2 * t]     = w0;
        g_slot_e[2 * t + 1] = i1; g_slot_r[2 * t + 1] = r1; g_slot_w[2 * t + 1] = w1;
    }
}

// ---------------- weight transpose -> fp16 (generic) -----------------------
__global__ void wt_convert_kernel(const float* __restrict__ W,
                                  fp16* __restrict__ Th, int K, int N)
{
    __shared__ float tile[64][68];
    size_t zoff = (size_t)blockIdx.z * K * N;
    int n0 = blockIdx.x * 64, k0 = blockIdx.y * 64;
    int tx = threadIdx.x & 15, ty = threadIdx.x >> 4;
#pragma unroll
    for (int i = 0; i < 4; i++) {
        int r = ty + 16 * i;
        *(float4*)&tile[r][tx * 4] = *(const float4*)(W + zoff + (size_t)(k0 + r) * N + n0 + tx * 4);
    }
    __syncthreads();
#pragma unroll
    for (int i = 0; i < 4; i++) {
        int n = ty + 16 * i, kk = tx * 4;
        size_t idx = zoff + (size_t)(n0 + n) * K + k0 + kk;
        *(uint2*)(Th + idx) = make_uint2(pack_h2(tile[kk][n], tile[kk + 1][n]),
                                         pack_h2(tile[kk + 2][n], tile[kk + 3][n]));
    }
}

// ---------------- fused wq/wk/wv transpose ----------------------------------
__global__ void wt_convert_qkv_kernel(const float* __restrict__ Wq,
                                      const float* __restrict__ Wk,
                                      const float* __restrict__ Wv,
                                      fp16* __restrict__ Th)
{
    __shared__ float tile[64][68];
    const float* W = (blockIdx.z == 0) ? Wq : (blockIdx.z == 1 ? Wk : Wv);
    size_t zoff = (size_t)blockIdx.z * DD * DD;
    int n0 = blockIdx.x * 64, k0 = blockIdx.y * 64;
    int tx = threadIdx.x & 15, ty = threadIdx.x >> 4;
#pragma unroll
    for (int i = 0; i < 4; i++) {
        int r = ty + 16 * i;
        *(float4*)&tile[r][tx * 4] = *(const float4*)(W + (size_t)(k0 + r) * DD + n0 + tx * 4);
    }
    __syncthreads();
#pragma unroll
    for (int i = 0; i < 4; i++) {
        int n = ty + 16 * i, kk = tx * 4;
        size_t idx = zoff + (size_t)(n0 + n) * DD + k0 + kk;
        *(uint2*)(Th + idx) = make_uint2(pack_h2(tile[kk][n], tile[kk + 1][n]),
                                         pack_h2(tile[kk + 2][n], tile[kk + 3][n]));
    }
}

#define GM_QKV  1
#define GM_RES  2
#define GM_MOE1 3
#define GM_MOE2 4
#define BUF_BYTES 65536
#define G_SMEM  (1024 + 3 * BUF_BYTES)   // 197632, 3-stage, warp-specialized

// ---------------- tcgen05 GEMM: C[256x256], warp-specialized pipeline ------
template<int MODE>
__global__ void __launch_bounds__(256, 1)
tc_gemm(const fp16* __restrict__ A, const fp16* __restrict__ B0,
        float* __restrict__ Cf, const float* __restrict__ Res,
        fp16* __restrict__ Ch, int M, int N, int K)
{
#if defined(__CUDA_ARCH__)
    extern __shared__ char sm[];
    int tid = threadIdx.x;
    int e  = blockIdx.z;
    int m0 = blockIdx.y * 256, n0 = blockIdx.x * 256;
    int Me = M;
    const fp16* B = B0;
    if (MODE == GM_MOE1 || MODE == GM_MOE2) {
        Me = g_cnt[e];
        if (m0 >= Me) return;
        B += (size_t)e * (size_t)K * N;
    } else if (MODE == GM_QKV) {
        B += (size_t)e * (size_t)K * N;
    }

#if defined(__CUDA_ARCH_FEAT_SM103_ALL)
    uint32_t sb = smem_u32(sm);
    int wid = tid >> 5, lid = tid & 31;
    int nk = K / 64;   // >= 16

    // mbarriers: fill_done[b] at sb+8+b*8 (224 arrivals); mma_done[b] at sb+32+b*8 (1)
    if (wid == 0) { TC_ALLOC(sb, 512); TC_RELINQ(); }
    if (tid == 0) {
#pragma unroll
        for (int b = 0; b < 3; b++) {
            mbar_init(sb + 8 + b * 8, 224);
            mbar_init(sb + 32 + b * 8, 1);
        }
    }
    __syncthreads();
    uint32_t tmem;
    asm volatile("ld.shared.b32 %0, [%1];" : "=r"(tmem) : "r"(sb));

    const uint32_t IDESC = (1u << 4) | (32u << 17) | (8u << 24);

    if (tid < 224) {
        // ---- producer: fill chunks, bounded by per-buffer MMA-done ----
        for (int f = 0; f < nk; f++) {
            int b = f % 3;
            if (f >= 3) mbar_wait(sb + 32 + b * 8, (uint32_t)((f / 3 - 1) & 1));
            uint32_t tb = sb + 1024 + (uint32_t)b * BUF_BYTES;
            for (int task = tid; task < 512; task += 224) {
                if (task < 256) {
                    int gr = m0 + task;
                    bool val = gr < Me;
                    size_t ri = 0;
                    if (val) {
                        if (MODE == GM_MOE1)      ri = (size_t)g_rowlist[e * TT + gr];
                        else if (MODE == GM_MOE2) ri = (size_t)e * TT + gr;
                        else                      ri = (size_t)gr;
                    }
                    const char* src = (const char*)(A + ri * (size_t)K + f * 64);
                    uint32_t sz = val ? 16u : 0u;
#pragma unroll
                    for (int j = 0; j < 8; j++) {
                        uint32_t off = (uint32_t)task * 128u + j * 16u;
                        uint32_t swz = off ^ ((off >> 3) & 0x70);
                        asm volatile("cp.async.cg.shared.global [%0], [%1], 16, %2;"
                                     :: "r"(tb + swz), "l"(src + j * 16), "r"(sz) : "memory");
                    }
                } else {
                    int row = task - 256;
                    const char* src = (const char*)(B + (size_t)(n0 + row) * K + f * 64);
#pragma unroll
                    for (int j = 0; j < 8; j++) {
                        uint32_t off = (uint32_t)row * 128u + j * 16u;
                        uint32_t swz = off ^ ((off >> 3) & 0x70);
                        asm volatile("cp.async.cg.shared.global [%0], [%1], 16;"
                                     :: "r"(tb + 32768 + swz), "l"(src + j * 16) : "memory");
                    }
                }
            }
            asm volatile("cp.async.mbarrier.arrive.noinc.shared::cta.b64 [%0];"
                         :: "r"(sb + 8 + b * 8) : "memory");
        }
    } else if (wid == 7) {
        // ---- consumer: wait fill-done, issue MMAs, commit ----
        if (elect1()) {
            for (int kc = 0; kc < nk; kc++) {
                int b = kc % 3;
                mbar_wait(sb + 8 + b * 8, (uint32_t)((kc / 3) & 1));
                asm volatile("fence.proxy.async.shared::cta;" ::: "memory");
                uint32_t tb = sb + 1024 + (uint32_t)b * BUF_BYTES;
                uint64_t dA0 = mk_desc(tb);
                uint64_t dA1 = mk_desc(tb + 16384);
                uint64_t dB  = mk_desc(tb + 32768);
#pragma unroll
                for (int s = 0; s < 4; s++) {
                    uint32_t en0 = (kc == 0 && s == 0) ? 0u : 1u;
                    mma_f16_ss(tmem,       dA0 + 2 * s, dB + 2 * s, IDESC, en0);
                    mma_f16_ss(tmem + 256, dA1 + 2 * s, dB + 2 * s, IDESC, en0);
                }
                tc_commit(sb + 32 + b * 8);
            }
        }
    }

    // all threads: wait final MMA commit (covers all prior MMAs in order)
    mbar_wait(sb + 32 + ((nk - 1) % 3) * 8, (uint32_t)(((nk - 1) / 3) & 1));
    TC_FENCE_AFTER();
    __syncthreads();

    // staged coalesced epilogue: TMEM -> smem (128x129 fp32) -> contiguous global
    int rw = wid & 3, cw = wid >> 2;
    float* Cs = (float*)(sm + 1024);
#pragma unroll 1
    for (int rb = 0; rb < 2; rb++) {
        int mb = m0 + rb * 128;
        int rows_here = Me - mb;
        if (rows_here <= 0) break;
        if (rows_here > 128) rows_here = 128;
#pragma unroll 1
        for (int p = 0; p < 2; p++) {
            uint32_t d0[32], d1[32];
            TC_LD_X32(d0, tmem + rb * 256 + p * 128 + cw * 64);
            TC_LD_X32(d1, tmem + rb * 256 + p * 128 + cw * 64 + 32);
            TC_WAIT_LD();
            TC_FENCE_BEFORE();
            __syncthreads();
            {
                int rr = rw * 32 + lid, cb = cw * 64;
#pragma unroll
                for (int j = 0; j < 32; j++) {
                    Cs[rr * 129 + cb + j]      = __uint_as_float(d0[j]);
                    Cs[rr * 129 + cb + 32 + j] = __uint_as_float(d1[j]);
                }
            }
            __syncthreads();
#pragma unroll 4
            for (int it = 0; it < 16; it++) {
                int idx4 = (it * 256 + tid) * 4;
                int rr = idx4 >> 7, cc = idx4 & 127;
                if (rr >= rows_here) continue;
                float v0 = Cs[rr * 129 + cc + 0], v1 = Cs[rr * 129 + cc + 1];
                float v2 = Cs[rr * 129 + cc + 2], v3 = Cs[rr * 129 + cc + 3];
                int colb = n0 + p * 128 + cc;
                if (MODE == GM_RES) {
                    size_t o = (size_t)(mb + rr) * N + colb;
                    float4 rs = *(const float4*)(Res + o);
                    *(float4*)(Cf + o) = make_float4(v0 + rs.x, v1 + rs.y, v2 + rs.z, v3 + rs.w);
                } else if (MODE == GM_MOE2) {
                    size_t o = ((size_t)e * TT + mb + rr) * N + colb;
                    uint2 ph; ph.x = pack_h2(v0, v1); ph.y = pack_h2(v2, v3);
                    *(uint2*)(g_Y + o) = ph;
                } else if (MODE == GM_MOE1) {
                    size_t o = ((size_t)e * TT + mb + rr) * N + colb;
                    uint2 ph;
                    ph.x = pack_h2(gelu_tanh(v0), gelu_tanh(v1));
                    ph.y = pack_h2(gelu_tanh(v2), gelu_tanh(v3));
                    *(uint2*)(Ch + o) = ph;
                } else {
                    int row = mb + rr;
                    int b2 = row >> 11, s5 = row & (SS - 1);
                    int h = colb >> 6, dh = colb & 63;
                    size_t o = (((size_t)(b2 * NH + h)) * SS + s5) * DH + dh;
                    uint2 ph; ph.x = pack_h2(v0, v1); ph.y = pack_h2(v2, v3);
                    *(uint2*)(g_qkv[e] + o) = ph;
                }
            }
            __syncthreads();
        }
    }
    if (wid == 0) { TC_DEALLOC(tmem, 512); }

#else
    // compact SIMT fallback (never runs when sm_103a SASS is loaded)
    for (int i = tid; i < 256 * 256; i += 256) {
        int rr = i >> 8, cc = i & 255;
        int row = m0 + rr;
        if (row >= Me) continue;
        size_t ri;
        if (MODE == GM_MOE1)      ri = (size_t)g_rowlist[e * TT + row];
        else if (MODE == GM_MOE2) ri = (size_t)e * TT + row;
        else                      ri = (size_t)row;
        float acc = 0.f;
        const fp16* ar = A + ri * (size_t)K;
        const fp16* br = B + (size_t)(n0 + cc) * K;
        for (int k = 0; k < K; k++)
            acc += __half2float(ar[k]) * __half2float(br[k]);
        if (MODE == GM_RES) { size_t o = (size_t)row * N + n0 + cc; Cf[o] = acc + Res[o]; }
        else if (MODE == GM_MOE2) g_Y[((size_t)e * TT + row) * N + n0 + cc] = __float2half_rn(acc);
        else if (MODE == GM_MOE1) Ch[((size_t)e * TT + row) * N + n0 + cc] = __float2half_rn(gelu_tanh(acc));
        else {
            int col = n0 + cc, b2 = row >> 11, s5 = row & (SS - 1);
            g_qkv[e][(((size_t)(b2 * NH + (col >> 6))) * SS + s5) * DH + (col & 63)] = __float2half_rn(acc);
        }
    }
#endif
#endif
}

// ---------------- tcgen05 flash attention (unchanged) ----------------------
#define SM_Q   1024
#define SM_K   17408
#define SM_VST 33792
#define SM_VT  50176
#define SM_P   66560
#define ATT_SMEM 100352

__global__ void __launch_bounds__(256, 2)
tc_attn(fp16* __restrict__ outh)
{
#if defined(__CUDA_ARCH__)
    extern __shared__ char sm[];
    int tid = threadIdx.x;
    int bh = blockIdx.x;
    int qt = blockIdx.y;

#if defined(__CUDA_ARCH_FEAT_SM103_ALL)
    uint32_t sb = smem_u32(sm);
    int wid = tid >> 5, lane = tid & 31;

    auto fill_kv = [&](int kt) {
        int arr = tid >> 7, r = tid & 127;
        const fp16* src = (arr == 0 ? g_qkv[1] : g_qkv[2]);
        uint32_t dstb = (arr == 0 ? sb + SM_K : sb + SM_VST);
        const char* s4 = (const char*)(src + ((size_t)bh * SS + kt * 128 + r) * DH);
        if (arr == 0) {
#pragma unroll
            for (int j = 0; j < 8; j++) {
                uint32_t off = (uint32_t)r * 128u + j * 16u;
                uint32_t swz = off ^ ((off >> 3) & 0x70);
                asm volatile("cp.async.cg.shared.global [%0], [%1], 16;"
                             :: "r"(dstb + swz), "l"(s4 + j * 16) : "memory");
            }
        } else {
#pragma unroll
            for (int j = 0; j < 8; j++)
                asm volatile("cp.async.cg.shared.global [%0], [%1], 16;"
                             :: "r"(dstb + (uint32_t)r * 128u + j * 16u), "l"(s4 + j * 16) : "memory");
        }
        asm volatile("cp.async.commit_group;" ::: "memory");
    };

    fill_kv(0);

    if (wid == 0) { TC_ALLOC(sb, 256); TC_RELINQ(); }
    if (tid == 0) { mbar_init(sb + 8, 1); mbar_init(sb + 16, 1); }
    __syncthreads();
    uint32_t tmem;
    asm volatile("ld.shared.b32 %0, [%1];" : "=r"(tmem) : "r"(sb));

    {
        int r = tid & 127, j0 = (tid >> 7) * 4;
        const uint4* s4 = (const uint4*)(g_qkv[0] + ((size_t)bh * SS + qt * 128 + r) * DH);
#pragma unroll
        for (int j = 0; j < 4; j++) {
            uint32_t off = (uint32_t)r * 128u + (j0 + j) * 16u;
            uint32_t swz = off ^ ((off >> 3) & 0x70);
            *(uint4*)(sm + SM_Q + swz) = s4[j0 + j];
        }
    }

    const uint32_t IDESC_S = (1u << 4) | (16u << 17) | (8u << 24);
    const uint32_t IDESC_O = (1u << 4) | (8u << 17)  | (8u << 24);
    int sph = 0, oph = 0;
    float lpart = 0.f;
    const int NKT = SS / 128;

    for (int kt = 0; kt < NKT; kt++) {
        if (kt > 0) { mbar_wait(sb + 16, (uint32_t)(oph & 1)); oph++; }
        asm volatile("cp.async.wait_group 0;" ::: "memory");
        asm volatile("fence.proxy.async.shared::cta;" ::: "memory");
        __syncthreads();

        if (wid == 0 && elect1()) {
            uint64_t dQ = mk_desc(sb + SM_Q);
            uint64_t dK = mk_desc(sb + SM_K);
#pragma unroll
            for (int ks = 0; ks < 4; ks++)
                mma_f16_ss(tmem, dQ + 2 * ks, dK + 2 * ks, IDESC_S, ks == 0 ? 0u : 1u);
            tc_commit(sb + 8);
        }

        {
            int d = tid & 63, shb = (tid >> 6) & 1, mh = tid >> 7;
            const unsigned short* vs = (const unsigned short*)(sm + SM_VST);
            char* vt = sm + SM_VT + shb * 8192;
#pragma unroll
            for (int i = 0; i < 16; i++) {
                int m = mh * 16 + i;
                int s0 = shb * 64 + 2 * m;
                uint32_t u = (uint32_t)vs[s0 * 64 + d] | ((uint32_t)vs[(s0 + 1) * 64 + d] << 16);
                uint32_t off = (uint32_t)d * 128u + m * 4u;
                uint32_t swz = off ^ ((off >> 3) & 0x70);
                *(uint32_t*)(vt + swz) = u;
            }
        }
        asm volatile("fence.proxy.async.shared::cta;" ::: "memory");
        __syncthreads();

        mbar_wait(sb + 8, (uint32_t)(sph & 1)); sph++;
        TC_FENCE_AFTER();

        if (kt + 1 < NKT) fill_kv(kt + 1);

        {
            int rw = wid & 3, cw = wid >> 2;
            uint32_t s0[32], s1[32];
            TC_LD_X32(s0, tmem + cw * 64);
            TC_LD_X32(s1, tmem + cw * 64 + 32);
            TC_WAIT_LD();
            TC_FENCE_BEFORE();
            int r = rw * 32 + lane;
            char* pb = sm + SM_P + cw * 16384;
#pragma unroll
            for (int m = 0; m < 32; m++) {
                int c0 = 2 * m, c1 = 2 * m + 1;
                float a = __uint_as_float(c0 < 32 ? s0[c0] : s1[c0 - 32]);
                float b = __uint_as_float(c1 < 32 ? s0[c1] : s1[c1 - 32]);
                float pa = __expf(a * 0.125f);
                float pbv = __expf(b * 0.125f);
                lpart += pa + pbv;
                uint32_t off = (uint32_t)r * 128u + m * 4u;
                uint32_t swz = off ^ ((off >> 3) & 0x70);
                *(uint32_t*)(pb + swz) = pack_h2(pa, pbv);
            }
        }
        asm volatile("fence.proxy.async.shared::cta;" ::: "memory");
        __syncthreads();

        if (wid == 0 && elect1()) {
#pragma unroll
            for (int kb = 0; kb < 2; kb++) {
                uint64_t dP = mk_desc(sb + SM_P + kb * 16384);
                uint64_t dV = mk_desc(sb + SM_VT + kb * 8192);
#pragma unroll
                for (int ks = 0; ks < 4; ks++) {
                    uint32_t en0 = (kt == 0 && kb == 0 && ks == 0) ? 0u : 1u;
                    mma_f16_ss(tmem + 128, dP + 2 * ks, dV + 2 * ks, IDESC_O, en0);
                }
            }
            tc_commit(sb + 16);
        }
    }
    mbar_wait(sb + 16, (uint32_t)(oph & 1)); oph++;
    TC_FENCE_AFTER();

    float* lred = (float*)(sm + SM_P);
    lred[tid] = lpart;
    __syncthreads();
    if (wid < 4) {
        uint32_t o0[32], o1[32];
        TC_LD_X32(o0, tmem + 128);
        TC_LD_X32(o1, tmem + 160);
        TC_WAIT_LD();
        TC_FENCE_BEFORE();
        int r = wid * 32 + lane;
        float inv = 1.f / (lred[r] + lred[r + 128]);
        int b = bh >> 4, h = bh & 15;
        int s = qt * 128 + r;
        uint32_t* ph = (uint32_t*)(outh + ((size_t)(b * SS + s)) * DD + h * 64);
#pragma unroll
        for (int m = 0; m < 32; m++) {
            int c0 = 2 * m, c1 = 2 * m + 1;
            float v0 = __uint_as_float(c0 < 32 ? o0[c0] : o1[c0 - 32]) * inv;
            float v1 = __uint_as_float(c1 < 32 ? o0[c1] : o1[c1 - 32]) * inv;
            ph[m] = pack_h2(v0, v1);
        }
    }
    __syncthreads();
    if (wid == 0) { TC_DEALLOC(tmem, 256); }

#else
    if (tid < 128) {
        int r = qt * 128 + tid;
        const fp16* Q = g_qkv[0] + ((size_t)bh * SS + r) * DH;
        float acc[DH];
        for (int d = 0; d < DH; d++) acc[d] = 0.f;
        float l = 0.f;
        for (int s = 0; s < SS; s++) {
            const fp16* Kp = g_qkv[1] + ((size_t)bh * SS + s) * DH;
            const fp16* Vp = g_qkv[2] + ((size_t)bh * SS + s) * DH;
            float sc = 0.f;
            for (int d = 0; d < DH; d++) sc += __half2float(Q[d]) * __half2float(Kp[d]);
            float p = expf(sc * 0.125f);
            l += p;
            for (int d = 0; d < DH; d++) acc[d] += p * __half2float(Vp[d]);
        }
        int b = bh >> 4, h = bh & 15;
        fp16* o = outh + ((size_t)(b * SS + r)) * DD + h * 64;
        for (int d = 0; d < DH; d++) o[d] = __float2half_rn(acc[d] / l);
    }
#endif
#endif
}

// ---------------- misc kernels ----------------
__global__ void zero_cnt_kernel() { if (threadIdx.x < NE) g_cnt[threadIdx.x] = 0; }

__global__ void loss_kernel(float* __restrict__ out, int out_size)
{
    int tid = threadIdx.x;
    __shared__ float red[256];
    __shared__ float sumsp[NE];
    __shared__ float sumz;
    float accp[NE];
#pragma unroll
    for (int e = 0; e < NE; e++) accp[e] = 0.f;
    float accz = 0.f;
    for (int t = tid; t < TT; t += 256) {
        float z = g_zz[t];
        accz += z * z;
#pragma unroll
        for (int e = 0; e < NE; e++) accp[e] += g_probs[t * NE + e];
    }
    red[tid] = accz; __syncthreads();
    for (int o = 128; o > 0; o >>= 1) { if (tid < o) red[tid] += red[tid + o]; __syncthreads(); }
    if (tid == 0) sumz = red[0];
    __syncthreads();
    for (int e = 0; e < NE; e++) {
        red[tid] = accp[e]; __syncthreads();
        for (int o = 128; o > 0; o >>= 1) { if (tid < o) red[tid] += red[tid + o]; __syncthreads(); }
        if (tid == 0) sumsp[e] = red[0];
        __syncthreads();
    }
    if (tid == 0) {
        float aux = 0.f;
        for (int e = 0; e < NE; e++)
            aux += ((float)g_cnt[e] / (float)TT) * (sumsp[e] / (float)TT);
        aux *= (float)NE / 2.f;
        float loss = aux + 0.001f * (sumz / (float)TT);
        for (int i = NMAIN; i < out_size; i++) out[i] = loss;
    }
}

__global__ void combine_kernel(float* __restrict__ out)
{
    int idx4 = (blockIdx.x * 256 + threadIdx.x) * 4;
    if (idx4 >= NMAIN) return;
    int t = idx4 >> 10, d = idx4 & 1023;
    int e0 = g_slot_e[2 * t], r0 = g_slot_r[2 * t];
    int e1 = g_slot_e[2 * t + 1], r1 = g_slot_r[2 * t + 1];
    float w0 = g_slot_w[2 * t], w1 = g_slot_w[2 * t + 1];
    float4 xv = *(const float4*)(g_x2 + idx4);
    uint2 y0u = *(const uint2*)(g_Y + ((size_t)e0 * TT + r0) * DD + d);
    uint2 y1u = *(const uint2*)(g_Y + ((size_t)e1 * TT + r1) * DD + d);
    __half2 a0 = *(__half2*)&y0u.x, a1 = *(__half2*)&y0u.y;
    __half2 b0 = *(__half2*)&y1u.x, b1 = *(__half2*)&y1u.y;
    float4 r;
    r.x = xv.x + w0 * __low2float(a0)  + w1 * __low2float(b0);
    r.y = xv.y + w0 * __high2float(a0) + w1 * __high2float(b0);
    r.z = xv.z + w0 * __low2float(a1)  + w1 * __low2float(b1);
    r.w = xv.w + w0 * __high2float(a1) + w1 * __high2float(b1);
    *(float4*)(out + idx4) = r;
}

// ---------------- launch ----------------
extern "C" void kernel_launch(void* const* d_in, const int* in_sizes, int n_in,
                              void* d_out, int out_size)
{
    const float* x   = (const float*)d_in[0];
    const float* ln1 = (const float*)d_in[1];
    const float* ln2 = (const float*)d_in[2];
    const float* wq  = (const float*)d_in[3];
    const float* wk  = (const float*)d_in[4];
    const float* wv  = (const float*)d_in[5];
    const float* wo  = (const float*)d_in[6];
    const float* wr  = (const float*)d_in[7];
    const float* w1  = (const float*)d_in[8];
    const float* w2  = (const float*)d_in[9];
    float* out = (float*)d_out;

    cudaFuncSetAttribute(tc_attn, cudaFuncAttributeMaxDynamicSharedMemorySize, ATT_SMEM);
    cudaFuncSetAttribute(tc_gemm<GM_QKV>,  cudaFuncAttributeMaxDynamicSharedMemorySize, G_SMEM);
    cudaFuncSetAttribute(tc_gemm<GM_RES>,  cudaFuncAttributeMaxDynamicSharedMemorySize, G_SMEM);
    cudaFuncSetAttribute(tc_gemm<GM_MOE1>, cudaFuncAttributeMaxDynamicSharedMemorySize, G_SMEM);
    cudaFuncSetAttribute(tc_gemm<GM_MOE2>, cudaFuncAttributeMaxDynamicSharedMemorySize, G_SMEM);

    fp16 *p_xn, *p_xn2, *p_ctx, *p_wpt, *p_w1t, *p_w2t, *p_H;
    float *p_x2;
    cudaGetSymbolAddress((void**)&p_xn,   g_xn);
    cudaGetSymbolAddress((void**)&p_xn2,  g_xn2);
    cudaGetSymbolAddress((void**)&p_ctx,  g_ctx);
    cudaGetSymbolAddress((void**)&p_x2,   g_x2);
    cudaGetSymbolAddress((void**)&p_wpt,  g_wpt);
    cudaGetSymbolAddress((void**)&p_w1t,  g_w1t);
    cudaGetSymbolAddress((void**)&p_w2t,  g_w2t);
    cudaGetSymbolAddress((void**)&p_H,    g_H);

    dim3 bt(256);
    wt_convert_qkv_kernel<<<dim3(DD/64, DD/64, 3), bt>>>(wq, wk, wv, p_wpt);
    rmsnorm_kernel<<<TT, 256>>>(x, ln1, p_xn);
    wt_convert_kernel<<<dim3(DD/64, DD/64, 1), bt>>>(wo, p_wpt + 3*DD*DD, DD, DD);
    // ncu slot: QKV projections
    tc_gemm<GM_QKV><<<dim3(DD/256, TT/256, 3), 256, G_SMEM>>>(
        p_xn, p_wpt, nullptr, nullptr, nullptr, TT, DD, DD);

    wt_convert_kernel<<<dim3(FF/64, DD/64, NE), bt>>>(w1, p_w1t, DD, FF);
    wt_convert_kernel<<<dim3(DD/64, FF/64, NE), bt>>>(w2, p_w2t, FF, DD);

    tc_attn<<<dim3(BB * NH, SS / 128), 256, ATT_SMEM>>>(p_ctx);

    tc_gemm<GM_RES><<<dim3(DD/256, TT/256, 1), 256, G_SMEM>>>(
        p_ctx, p_wpt + 3*DD*DD, p_x2, x, nullptr, TT, DD, DD);

    zero_cnt_kernel<<<1, 32>>>();
    norm2_router_kernel<<<TT, 256>>>(p_x2, ln2, wr, p_xn2);
    loss_kernel<<<1, 256>>>(out, out_size);

    tc_gemm<GM_MOE1><<<dim3(FF/256, TT/256, NE), 256, G_SMEM>>>(
        p_xn2, p_w1t, nullptr, nullptr, p_H, TT, FF, DD);
    tc_gemm<GM_MOE2><<<dim3(DD/256, TT/256, NE), 256, G_SMEM>>>(
        p_H, p_w2t, nullptr, nullptr, nullptr, TT, DD, FF);

    combine_kernel<<<(NMAIN/4 + 255) / 256, 256>>>(out);
}